// round 9
// baseline (speedup 1.0000x reference)
#include <cuda_runtime.h>
#include <cuda_bf16.h>
#include <math.h>
#include <stdint.h>

#define NN 100000
#define GG 6000
#define EE 400000

// ---------------- scratch (static __device__ — no allocs allowed) ----------------
__device__ float g_q  [NN * 128];
__device__ float g_k  [GG * 128];
__device__ float g_val[GG * 128];
__device__ float g_ms [NN * 128];
__device__ float g_mv [NN * 384];
__device__ float g_t0 [NN * 128];
__device__ float g_t4 [NN * 128];
__device__ float g_t5 [NN * 128];
__device__ float g_v1 [NN * 384];
__device__ float g_v2 [NN * 384];
__device__ float g_Pp [GG * 512];
__device__ float g_Ps [GG * 512];
__device__ uint32_t g_whi[9 * 8192];
__device__ uint32_t g_wlo[9 * 8192];
// group-sort scratch
__device__ int g_cnt [GG];
__device__ int g_cur [GG];
__device__ int g_perm[EE];

__device__ __forceinline__ float silu_f(float x) {
    return x / (1.0f + __expf(-x));
}

// blocked-atom SW128 byte offset for a [128 rows][128 cols bf16] tile
__device__ __forceinline__ uint32_t blk_off(int row, int col) {
    uint32_t off = (uint32_t)((row >> 3) + (col >> 6) * 16) * 1024u
                 + (uint32_t)(row & 7) * 128u + (uint32_t)(col & 63) * 2u;
    return off ^ ((off >> 3) & 0x70);
}

// ---------------- counting sort of edges by group ----------------
__global__ void hist_kernel(const int* __restrict__ gidx) {
    int e = blockIdx.x * 256 + threadIdx.x;
    if (e < EE) atomicAdd(&g_cnt[gidx[e]], 1);
}

__global__ void scan_kernel() {
    __shared__ int part[1024];
    int tid = threadIdx.x;
    int c0 = tid * 6;
    int local[6];
    int s = 0;
    #pragma unroll
    for (int i = 0; i < 6; i++) {
        int v = (c0 + i < GG) ? g_cnt[c0 + i] : 0;
        local[i] = s; s += v;
    }
    part[tid] = s;
    __syncthreads();
    for (int off = 1; off < 1024; off <<= 1) {
        int v = (tid >= off) ? part[tid - off] : 0;
        __syncthreads();
        part[tid] += v;
        __syncthreads();
    }
    int base = (tid > 0) ? part[tid - 1] : 0;
    #pragma unroll
    for (int i = 0; i < 6; i++)
        if (c0 + i < GG) g_cur[c0 + i] = base + local[i];
}

__global__ void scatter_kernel(const int* __restrict__ gidx) {
    int e = blockIdx.x * 256 + threadIdx.x;
    if (e < EE) {
        int pos = atomicAdd(&g_cur[gidx[e]], 1);
        g_perm[pos] = e;
    }
}

// ---------------- weight conversion: W[k][n] fp32 -> B[n][k] bf16 hi/lo ----------------
__global__ void wconv_kernel(
    const float* __restrict__ W0, const float* __restrict__ W1,
    const float* __restrict__ W2, const float* __restrict__ W3,
    const float* __restrict__ W4, const float* __restrict__ W5,
    const float* __restrict__ W6, const float* __restrict__ W7,
    const float* __restrict__ W8)
{
    const float* Ws[9] = {W0, W1, W2, W3, W4, W5, W6, W7, W8};
    int gidx = blockIdx.x * 256 + threadIdx.x;
    if (gidx >= 9 * 8192) return;
    int w = gidx >> 13, p = gidx & 8191;
    int n = p >> 6, k2 = (p & 63) * 2;
    const float* W = Ws[w];
    float x0 = W[k2 * 128 + n], x1 = W[(k2 + 1) * 128 + n];
    __nv_bfloat16 h0 = __float2bfloat16(x0), h1 = __float2bfloat16(x1);
    float r0 = x0 - __bfloat162float(h0), r1 = x1 - __bfloat162float(h1);
    __nv_bfloat16 l0 = __float2bfloat16(r0), l1 = __float2bfloat16(r1);
    uint32_t o = blk_off(n, k2) >> 2;
    g_whi[w * 8192 + o] = (uint32_t)__bfloat16_as_ushort(h0)
                        | ((uint32_t)__bfloat16_as_ushort(h1) << 16);
    g_wlo[w * 8192 + o] = (uint32_t)__bfloat16_as_ushort(l0)
                        | ((uint32_t)__bfloat16_as_ushort(l1) << 16);
}

// ---------------- arch-specific PTX helpers (guarded) ----------------
#if defined(__CUDA_ARCH_FEAT_SM103_ALL) || !defined(__CUDA_ARCH__)
#define HAVE_TCGEN05 1
#else
#define HAVE_TCGEN05 0
#endif

__device__ __forceinline__ uint32_t smem_u32(const void* p) {
    uint32_t a;
    asm("{ .reg .u64 t; cvta.to.shared.u64 t, %1; cvt.u32.u64 %0, t; }"
        : "=r"(a) : "l"(p));
    return a;
}

#if HAVE_TCGEN05
__device__ __forceinline__ uint32_t elect1() {
    uint32_t p;
    asm volatile("{\n\t.reg .pred p;\n\telect.sync _|p, 0xFFFFFFFF;\n\t"
                 "selp.b32 %0, 1, 0, p;\n\t}" : "=r"(p));
    return p;
}
__device__ __forceinline__ void mma_f16_ss(uint32_t d, uint64_t a, uint64_t b,
                                           uint32_t idesc, uint32_t en) {
    asm volatile("{\n\t.reg .pred p;\n\tsetp.ne.u32 p, %5, 0;\n\t"
                 "tcgen05.mma.cta_group::1.kind::f16 [%0], %1, %2, %3, {%4,%4,%4,%4}, p;\n\t}"
                 :: "r"(d), "l"(a), "l"(b), "r"(idesc), "r"(0u), "r"(en) : "memory");
}
__device__ __forceinline__ void mbar_wait(uint32_t mbar, uint32_t parity) {
    uint32_t done;
    asm volatile("{\n\t.reg .pred p;\n\t"
                 "mbarrier.try_wait.parity.acquire.cta.shared::cta.b64 p, [%1], %2;\n\t"
                 "selp.b32 %0, 1, 0, p;\n\t}"
                 : "=r"(done) : "r"(mbar), "r"(parity) : "memory");
    if (!done) {
        asm volatile("{\n\t.reg .pred P1;\n\t"
                     "WAIT_LOOP_%=:\n\t"
                     "mbarrier.try_wait.parity.acquire.cta.shared::cta.b64 P1, [%0], %1, 0x989680;\n\t"
                     "@P1 bra.uni WAIT_DONE_%=;\n\t"
                     "bra.uni WAIT_LOOP_%=;\n\t"
                     "WAIT_DONE_%=:\n\t}"
                     :: "r"(mbar), "r"(parity) : "memory");
    }
}
#define LDTM_X32(r, addr) \
    asm volatile( \
        "tcgen05.ld.sync.aligned.32x32b.x32.b32 " \
        "{%0, %1, %2, %3, %4, %5, %6, %7, " \
        " %8, %9, %10, %11, %12, %13, %14, %15, " \
        " %16, %17, %18, %19, %20, %21, %22, %23, " \
        " %24, %25, %26, %27, %28, %29, %30, %31}, [%32];" \
        : "=r"((r)[0]),  "=r"((r)[1]),  "=r"((r)[2]),  "=r"((r)[3]), \
          "=r"((r)[4]),  "=r"((r)[5]),  "=r"((r)[6]),  "=r"((r)[7]), \
          "=r"((r)[8]),  "=r"((r)[9]),  "=r"((r)[10]), "=r"((r)[11]), \
          "=r"((r)[12]), "=r"((r)[13]), "=r"((r)[14]), "=r"((r)[15]), \
          "=r"((r)[16]), "=r"((r)[17]), "=r"((r)[18]), "=r"((r)[19]), \
          "=r"((r)[20]), "=r"((r)[21]), "=r"((r)[22]), "=r"((r)[23]), \
          "=r"((r)[24]), "=r"((r)[25]), "=r"((r)[26]), "=r"((r)[27]), \
          "=r"((r)[28]), "=r"((r)[29]), "=r"((r)[30]), "=r"((r)[31]) \
        : "r"(addr))
#endif  // HAVE_TCGEN05

// ---------------- pipelined tcgen05 GEMM: up to 3 weights, TMEM ping-pong ----------------
// mode 0: C = A@W (+bias). mode 1: C = g_mv + g_t0[row/3] * (A@W)   (dv fusion)
#define SM_TMEM 0
#define SM_MB0  8
#define SM_MB1  16
#define SM_MB2  24
#define SM_AHI  1024
#define SM_ALO  33792
#define SM_B0HI 66560
#define SM_B0LO 99328
#define SM_B1HI 132096
#define SM_B1LO 164864
#define TC_SMEM 197632
#define TMEM_COLS 512

#if HAVE_TCGEN05
__device__ __forceinline__ void tc_copyB(char* smem, uint32_t dsthi, uint32_t dstlo,
                                         int w, int tid)
{
    const uint4* shi = (const uint4*)(g_whi + w * 8192);
    const uint4* slo = (const uint4*)(g_wlo + w * 8192);
    uint4* dhi = (uint4*)(smem + dsthi);
    uint4* dlo = (uint4*)(smem + dstlo);
    for (int i = tid; i < 2048; i += 256) { dhi[i] = shi[i]; dlo[i] = slo[i]; }
}

__device__ __forceinline__ void tc_issue_mma(uint32_t tmem_d, uint64_t ahi, uint64_t alo,
                                             uint64_t bhi, uint64_t blo, uint32_t mbar)
{
    const uint32_t IDESC = (1u << 4) | (1u << 7) | (1u << 10) | (16u << 17) | (8u << 24);
    uint32_t en = 0;
    #pragma unroll
    for (int kc = 0; kc < 8; kc++) {
        uint64_t ko = (uint64_t)((kc & 3) * 2 + (kc >> 2) * 1024);
        mma_f16_ss(tmem_d, ahi + ko, bhi + ko, IDESC, en); en = 1;
    }
    #pragma unroll
    for (int kc = 0; kc < 8; kc++) {
        uint64_t ko = (uint64_t)((kc & 3) * 2 + (kc >> 2) * 1024);
        mma_f16_ss(tmem_d, ahi + ko, blo + ko, IDESC, 1);
    }
    #pragma unroll
    for (int kc = 0; kc < 8; kc++) {
        uint64_t ko = (uint64_t)((kc & 3) * 2 + (kc >> 2) * 1024);
        mma_f16_ss(tmem_d, alo + ko, bhi + ko, IDESC, 1);
    }
    asm volatile("tcgen05.commit.cta_group::1.mbarrier::arrive::one.shared::cluster.b64 [%0];"
                 :: "r"(mbar) : "memory");
}

__device__ __forceinline__ void tc_epilogue(uint32_t tmem_d, int M, int row0,
                                            int wid, int lane, int mode,
                                            const float* bias, float* C)
{
    if (wid >= 4) return;
    int gr = row0 + wid * 32 + lane;
    #pragma unroll 1
    for (int cb = 0; cb < 4; cb++) {
        uint32_t d[32];
        LDTM_X32(d, tmem_d + cb * 32);
        asm volatile("tcgen05.wait::ld.sync.aligned;" ::: "memory");
        if (gr < M) {
            float* dst = C + (size_t)gr * 128 + cb * 32;
            if (mode == 1) {
                const float4* mvp = (const float4*)(g_mv + (size_t)gr * 128 + cb * 32);
                const float4* t0p = (const float4*)(g_t0 + (size_t)(gr / 3) * 128 + cb * 32);
                #pragma unroll
                for (int q = 0; q < 8; q++) {
                    float4 mv = mvp[q], t0 = t0p[q];
                    float4 o;
                    o.x = mv.x + t0.x * __uint_as_float(d[q * 4 + 0]);
                    o.y = mv.y + t0.y * __uint_as_float(d[q * 4 + 1]);
                    o.z = mv.z + t0.z * __uint_as_float(d[q * 4 + 2]);
                    o.w = mv.w + t0.w * __uint_as_float(d[q * 4 + 3]);
                    ((float4*)dst)[q] = o;
                }
            } else {
                #pragma unroll
                for (int q = 0; q < 8; q++) {
                    float4 o;
                    o.x = __uint_as_float(d[q * 4 + 0]);
                    o.y = __uint_as_float(d[q * 4 + 1]);
                    o.z = __uint_as_float(d[q * 4 + 2]);
                    o.w = __uint_as_float(d[q * 4 + 3]);
                    if (bias) {
                        const float* bb = bias + cb * 32 + q * 4;
                        o.x += bb[0]; o.y += bb[1]; o.z += bb[2]; o.w += bb[3];
                    }
                    ((float4*)dst)[q] = o;
                }
            }
        }
    }
}
#endif  // HAVE_TCGEN05

__global__ __launch_bounds__(256, 1) __cluster_dims__(1, 1, 1)
void tc_gemm(const float* __restrict__ A, int M,
             int w0, int m0, const float* __restrict__ W0f, const float* __restrict__ b0, float* __restrict__ C0,
             int w1, int m1, const float* __restrict__ W1f, const float* __restrict__ b1, float* __restrict__ C1,
             int w2, int m2, const float* __restrict__ W2f, const float* __restrict__ b2, float* __restrict__ C2)
{
#if HAVE_TCGEN05
    extern __shared__ char smem[];
    uint32_t sb = smem_u32(smem);
    int tid = threadIdx.x, wid = tid >> 5, lane = tid & 31;
    int row0 = blockIdx.x * 128;

    if (wid == 0)
        asm volatile("tcgen05.alloc.cta_group::1.sync.aligned.shared::cta.b32 [%0], %1;"
                     :: "r"(sb + SM_TMEM), "r"((uint32_t)TMEM_COLS) : "memory");
    if (tid == 0) {
        asm volatile("mbarrier.init.shared.b64 [%0], 1;" :: "r"(sb + SM_MB0) : "memory");
        asm volatile("mbarrier.init.shared.b64 [%0], 1;" :: "r"(sb + SM_MB1) : "memory");
        asm volatile("mbarrier.init.shared.b64 [%0], 1;" :: "r"(sb + SM_MB2) : "memory");
    }
    __syncthreads();
    uint32_t tmem;
    asm volatile("ld.shared.b32 %0, [%1];" : "=r"(tmem) : "r"(sb + SM_TMEM));

    for (int p = tid; p < 8192; p += 256) {
        int r = p >> 6, k2 = (p & 63) * 2;
        float2 x = make_float2(0.f, 0.f);
        if (row0 + r < M) x = *(const float2*)(A + (size_t)(row0 + r) * 128 + k2);
        __nv_bfloat16 h0 = __float2bfloat16(x.x), h1 = __float2bfloat16(x.y);
        float r0f = x.x - __bfloat162float(h0), r1f = x.y - __bfloat162float(h1);
        __nv_bfloat16 l0 = __float2bfloat16(r0f), l1 = __float2bfloat16(r1f);
        uint32_t hiw = (uint32_t)__bfloat16_as_ushort(h0)
                     | ((uint32_t)__bfloat16_as_ushort(h1) << 16);
        uint32_t low = (uint32_t)__bfloat16_as_ushort(l0)
                     | ((uint32_t)__bfloat16_as_ushort(l1) << 16);
        uint32_t off = blk_off(r, k2);
        *(uint32_t*)(smem + SM_AHI + off) = hiw;
        *(uint32_t*)(smem + SM_ALO + off) = low;
    }

    const uint64_t DESCB = (2ull << 61) | (1ull << 46) | (64ull << 32) | (1ull << 16);
    uint64_t ahi  = DESCB | ((uint64_t)((sb + SM_AHI)  >> 4) & 0x3FFF);
    uint64_t alo  = DESCB | ((uint64_t)((sb + SM_ALO)  >> 4) & 0x3FFF);
    uint64_t b0hi = DESCB | ((uint64_t)((sb + SM_B0HI) >> 4) & 0x3FFF);
    uint64_t b0lo = DESCB | ((uint64_t)((sb + SM_B0LO) >> 4) & 0x3FFF);
    uint64_t b1hi = DESCB | ((uint64_t)((sb + SM_B1HI) >> 4) & 0x3FFF);
    uint64_t b1lo = DESCB | ((uint64_t)((sb + SM_B1LO) >> 4) & 0x3FFF);

    tc_copyB(smem, SM_B0HI, SM_B0LO, w0, tid);
    asm volatile("fence.proxy.async.shared::cta;" ::: "memory");
    __syncthreads();
    if (wid == 0 && elect1())
        tc_issue_mma(tmem, ahi, alo, b0hi, b0lo, sb + SM_MB0);

    if (w1 >= 0) {
        tc_copyB(smem, SM_B1HI, SM_B1LO, w1, tid);
        asm volatile("fence.proxy.async.shared::cta;" ::: "memory");
        __syncthreads();
        if (wid == 0 && elect1())
            tc_issue_mma(tmem + 128, ahi, alo, b1hi, b1lo, sb + SM_MB1);
    }

    mbar_wait(sb + SM_MB0, 0);
    asm volatile("tcgen05.fence::after_thread_sync;" ::: "memory");
    if (w2 >= 0) {
        tc_copyB(smem, SM_B0HI, SM_B0LO, w2, tid);
        asm volatile("fence.proxy.async.shared::cta;" ::: "memory");
        __syncthreads();
        if (wid == 0 && elect1())
            tc_issue_mma(tmem + 256, ahi, alo, b0hi, b0lo, sb + SM_MB2);
    }

    tc_epilogue(tmem, M, row0, wid, lane, m0, b0, C0);
    if (w1 >= 0) {
        mbar_wait(sb + SM_MB1, 0);
        asm volatile("tcgen05.fence::after_thread_sync;" ::: "memory");
        tc_epilogue(tmem + 128, M, row0, wid, lane, m1, b1, C1);
    }
    if (w2 >= 0) {
        mbar_wait(sb + SM_MB2, 0);
        asm volatile("tcgen05.fence::after_thread_sync;" ::: "memory");
        tc_epilogue(tmem + 256, M, row0, wid, lane, m2, b2, C2);
    }
    asm volatile("tcgen05.fence::before_thread_sync;" ::: "memory");
    __syncthreads();

    if (tid == 0) {
        asm volatile("mbarrier.inval.shared.b64 [%0];" :: "r"(sb + SM_MB0) : "memory");
        asm volatile("mbarrier.inval.shared.b64 [%0];" :: "r"(sb + SM_MB1) : "memory");
        asm volatile("mbarrier.inval.shared.b64 [%0];" :: "r"(sb + SM_MB2) : "memory");
    }
    __syncthreads();
    if (wid == 0)
        asm volatile("tcgen05.dealloc.cta_group::1.sync.aligned.b32 %0, %1;"
                     :: "r"(tmem), "r"((uint32_t)TMEM_COLS));

#else  // ---------------- SIMT fp32 fallback (plain sm_103 pass) ----------------
    extern __shared__ float smf[];
    float* sA = smf;
    float* sW = smf + 16384;
    int tid = threadIdx.x;
    int row0 = blockIdx.x * 128;

    for (int i = tid; i < 4096; i += 256) {
        int r  = i >> 5;
        int gr = row0 + r;
        float4 v = make_float4(0.f, 0.f, 0.f, 0.f);
        if (gr < M) v = ((const float4*)A)[(size_t)gr * 32 + (i & 31)];
        ((float4*)sA)[i] = v;
    }

    const float* Wf[3] = {W0f, W1f, W2f};
    const float* bpf[3] = {b0, b1, b2};
    float* cpf[3] = {C0, C1, C2};
    int widxf[3] = {w0, w1, w2};
    int modef[3] = {m0, m1, m2};

    #pragma unroll 1
    for (int j = 0; j < 3; j++) {
        if (widxf[j] < 0) break;
        __syncthreads();
        for (int i = tid; i < 4096; i += 256)
            ((float4*)sW)[i] = ((const float4*)Wf[j])[i];
        __syncthreads();

        int rb = tid >> 4, cb = tid & 15;
        float acc[8][8];
        #pragma unroll
        for (int i = 0; i < 8; i++)
            #pragma unroll
            for (int q = 0; q < 8; q++) acc[i][q] = 0.f;

        #pragma unroll 4
        for (int k = 0; k < 128; k++) {
            float4 wv0 = *(const float4*)&sW[k * 128 + cb * 8];
            float4 wv1 = *(const float4*)&sW[k * 128 + cb * 8 + 4];
            float w[8] = {wv0.x, wv0.y, wv0.z, wv0.w, wv1.x, wv1.y, wv1.z, wv1.w};
            float a[8];
            #pragma unroll
            for (int i = 0; i < 8; i++) a[i] = sA[(rb * 8 + i) * 128 + k];
            #pragma unroll
            for (int i = 0; i < 8; i++)
                #pragma unroll
                for (int q = 0; q < 8; q++) acc[i][q] += a[i] * w[q];
        }

        #pragma unroll
        for (int i = 0; i < 8; i++) {
            int gr = row0 + rb * 8 + i;
            if (gr < M) {
                float* dst = cpf[j] + (size_t)gr * 128 + cb * 8;
                for (int q = 0; q < 8; q++) {
                    float o = acc[i][q];
                    if (modef[j] == 1)
                        o = g_mv[(size_t)gr * 128 + cb * 8 + q]
                          + g_t0[(size_t)(gr / 3) * 128 + cb * 8 + q] * o;
                    else if (bpf[j]) o += bpf[j][cb * 8 + q];
                    dst[q] = o;
                }
            }
        }
    }
#endif
}

// ---------------- P precompute ----------------
__global__ void pprep_kernel(const float* __restrict__ Wp1,
                             const float* __restrict__ Ws1)
{
    int idx = blockIdx.x * blockDim.x + threadIdx.x;
    if (idx >= GG * 512) return;
    int g  = idx >> 9;
    int hc = idx & 511;
    int h  = hc >> 6, c = hc & 63;
    const float* vp = g_val + (size_t)g * 128 + h * 16;
    float sp = 0.f, ss = 0.f;
    #pragma unroll
    for (int i = 0; i < 16; i++) {
        float v = vp[i];
        int wrow = (h * 16 + i) * 64 + c;
        sp += v * Wp1[wrow];
        ss += v * Ws1[wrow];
    }
    g_Pp[idx] = sp;
    g_Ps[idx] = ss;
}

// ---------------- fused edge kernel (group-sorted via g_perm) ----------------
#define EO_WP2  0
#define EO_WS2  8192
#define EO_HP   16384
#define EO_HS   20480
#define EO_ATT  24576
#define EO_BP1  25088
#define EO_BS1  25152
#define EO_BP2  25216
#define EO_BS2  25344
#define EO_U    25472
#define EO_N    25664
#define EO_G    25728
#define EO_E    25792
#define EDGE_SMEM_FLOATS 25856

__global__ __launch_bounds__(256, 2) void edge_kernel(
    const int*   __restrict__ node_idx,
    const int*   __restrict__ group_idx,
    const float* __restrict__ edge_attr,
    const float* __restrict__ edge_vec,
    const float* __restrict__ bp1, const float* __restrict__ bs1,
    const float* __restrict__ Wp2, const float* __restrict__ bp2,
    const float* __restrict__ Ws2, const float* __restrict__ bs2,
    const float* __restrict__ gvec)
{
    extern __shared__ float sm[];
    float* sWp2  = sm + EO_WP2;
    float* sWs2  = sm + EO_WS2;
    float* s_hp  = sm + EO_HP;
    float* s_hs  = sm + EO_HS;
    float* s_attn= sm + EO_ATT;
    float* s_bp1 = sm + EO_BP1;
    float* s_bs1 = sm + EO_BS1;
    float* s_bp2 = sm + EO_BP2;
    float* s_bs2 = sm + EO_BS2;
    float* s_u   = sm + EO_U;
    int*   s_n   = (int*)(sm + EO_N);
    int*   s_g   = (int*)(sm + EO_G);
    int*   s_e   = (int*)(sm + EO_E);

    int tid = threadIdx.x;

    for (int i = tid; i < 2048; i += 256) {
        ((float4*)sWp2)[i] = ((const float4*)Wp2)[i];
        ((float4*)sWs2)[i] = ((const float4*)Ws2)[i];
    }
    if (tid < 64)  { s_bp1[tid] = bp1[tid]; s_bs1[tid] = bs1[tid]; }
    if (tid < 128) { s_bp2[tid] = bp2[tid]; s_bs2[tid] = bs2[tid]; }
    __syncthreads();

    const int ntiles = EE / 64;
    for (int t = blockIdx.x; t < ntiles; t += gridDim.x) {
        int e0 = t * 64;

        if (tid < 64) {
            int e = g_perm[e0 + tid];          // group-sorted order
            s_e[tid] = e;
            s_n[tid] = node_idx[e];
            s_g[tid] = group_idx[e];
            s_u[tid * 3 + 0] = -edge_vec[e * 3 + 0];
            s_u[tid * 3 + 1] = -edge_vec[e * 3 + 1];
            s_u[tid * 3 + 2] = -edge_vec[e * 3 + 2];
        }
        __syncthreads();

        #pragma unroll
        for (int p = tid; p < 512; p += 256) {
            int le = p >> 3, h = p & 7;
            const float4* qp = (const float4*)(g_q + (size_t)s_n[le] * 128 + h * 16);
            const float4* kp = (const float4*)(g_k + (size_t)s_g[le] * 128 + h * 16);
            const float4* ep = (const float4*)(edge_attr + (size_t)s_e[le] * 128 + h * 16);
            float dot = 0.f;
            #pragma unroll
            for (int c = 0; c < 4; c++) {
                float4 qv = qp[c], kv = kp[c], ev = ep[c];
                dot += qv.x * kv.x * ev.x + qv.y * kv.y * ev.y
                     + qv.z * kv.z * ev.z + qv.w * kv.w * ev.w;
            }
            s_attn[le * 8 + h] = silu_f(dot * 0.25f);
        }
        __syncthreads();

        for (int i4 = tid; i4 < 2048; i4 += 256) {
            int le = i4 >> 5, j4 = i4 & 31;
            float4 v = ((const float4*)(g_val + (size_t)s_g[le] * 128))[j4];
            float  a = s_attn[le * 8 + (j4 >> 2)];
            float4 m = make_float4(v.x * a, v.y * a, v.z * a, v.w * a);
            atomicAdd((float4*)(g_ms + (size_t)s_n[le] * 128 + j4 * 4), m);
        }

        {
            int le = tid >> 2, cq = tid & 3, c0 = cq * 16;
            int g = s_g[le];
            float at[8];
            #pragma unroll
            for (int h = 0; h < 8; h++) at[h] = s_attn[le * 8 + h];
            float hp[16], hs[16];
            #pragma unroll
            for (int j = 0; j < 16; j++) { hp[j] = 0.f; hs[j] = 0.f; }
            const float4* Pp4 = (const float4*)(g_Pp + (size_t)g * 512);
            const float4* Ps4 = (const float4*)(g_Ps + (size_t)g * 512);
            #pragma unroll
            for (int h = 0; h < 8; h++) {
                int base = h * 16 + cq * 4;
                float ah = at[h];
                #pragma unroll
                for (int q = 0; q < 4; q++) {
                    float4 p = Pp4[base + q];
                    float4 s = Ps4[base + q];
                    hp[q*4+0] += ah * p.x; hp[q*4+1] += ah * p.y;
                    hp[q*4+2] += ah * p.z; hp[q*4+3] += ah * p.w;
                    hs[q*4+0] += ah * s.x; hs[q*4+1] += ah * s.y;
                    hs[q*4+2] += ah * s.z; hs[q*4+3] += ah * s.w;
                }
            }
            #pragma unroll
            for (int j = 0; j < 16; j++) {
                s_hp[le * 64 + c0 + j] = silu_f(hp[j] + s_bp1[c0 + j]);
                s_hs[le * 64 + c0 + j] = silu_f(hs[j] + s_bs1[c0 + j]);
            }
        }
        __syncthreads();

        {
            int rg = tid >> 4, cg = tid & 15;
            float sp[4][8], sv[4][8];
            #pragma unroll
            for (int i = 0; i < 4; i++)
                #pragma unroll
                for (int j = 0; j < 8; j++) { sp[i][j] = 0.f; sv[i][j] = 0.f; }

            #pragma unroll 2
            for (int k = 0; k < 64; k++) {
                float hp[4], hs[4];
                #pragma unroll
                for (int i = 0; i < 4; i++) {
                    hp[i] = s_hp[(rg * 4 + i) * 64 + k];
                    hs[i] = s_hs[(rg * 4 + i) * 64 + k];
                }
                float4 wpa = *(const float4*)&sWp2[k * 128 + cg * 8];
                float4 wpb = *(const float4*)&sWp2[k * 128 + cg * 8 + 4];
                float4 wsa = *(const float4*)&sWs2[k * 128 + cg * 8];
                float4 wsb = *(const float4*)&sWs2[k * 128 + cg * 8 + 4];
                float wp[8] = {wpa.x, wpa.y, wpa.z, wpa.w, wpb.x, wpb.y, wpb.z, wpb.w};
                float ws[8] = {wsa.x, wsa.y, wsa.z, wsa.w, wsb.x, wsb.y, wsb.z, wsb.w};
                #pragma unroll
                for (int i = 0; i < 4; i++)
                    #pragma unroll
                    for (int j = 0; j < 8; j++) {
                        sp[i][j] += hp[i] * wp[j];
                        sv[i][j] += hs[i] * ws[j];
                    }
            }

            float bp[8], bs[8];
            #pragma unroll
            for (int j = 0; j < 8; j++) { bp[j] = s_bp2[cg * 8 + j]; bs[j] = s_bs2[cg * 8 + j]; }

            #pragma unroll
            for (int i = 0; i < 4; i++) {
                int le = rg * 4 + i;
                int n = s_n[le], g = s_g[le];
                float spv[8], svv[8];
                #pragma unroll
                for (int j = 0; j < 8; j++) { spv[j] = sp[i][j] + bp[j]; svv[j] = sv[i][j] + bs[j]; }
                #pragma unroll
                for (int d = 0; d < 3; d++) {
                    float ud = s_u[le * 3 + d];
                    const float* gv = gvec + (size_t)g * 384 + d * 128 + cg * 8;
                    float4 g0 = *(const float4*)gv;
                    float4 g1 = *(const float4*)(gv + 4);
                    float4 o0 = make_float4(spv[0] * ud + svv[0] * g0.x,
                                            spv[1] * ud + svv[1] * g0.y,
                                            spv[2] * ud + svv[2] * g0.z,
                                            spv[3] * ud + svv[3] * g0.w);
                    float4 o1 = make_float4(spv[4] * ud + svv[4] * g1.x,
                                            spv[5] * ud + svv[5] * g1.y,
                                            spv[6] * ud + svv[6] * g1.z,
                                            spv[7] * ud + svv[7] * g1.w);
                    float* dst = g_mv + (size_t)n * 384 + d * 128 + cg * 8;
                    atomicAdd((float4*)dst, o0);
                    atomicAdd((float4*)(dst + 4), o1);
                }
            }
        }
        __syncthreads();
    }
}

// ---------------- finalize: dx only (dv fused into tc_gemm epilogue) ----------------
__global__ void finalize_kernel(float* __restrict__ out) {
    int idx = blockIdx.x * blockDim.x + threadIdx.x;
    if (idx >= NN * 32) return;
    int n = idx >> 5, j4 = idx & 31;
    size_t off = (size_t)n * 32 + j4;
    float4 t4 = ((const float4*)g_t4)[off];
    float4 t5 = ((const float4*)g_t5)[off];
    float4 s3 = make_float4(0.f, 0.f, 0.f, 0.f);
    #pragma unroll
    for (int d = 0; d < 3; d++) {
        size_t roff = ((size_t)n * 3 + d) * 32 + j4;
        float4 v1 = ((const float4*)g_v1)[roff];
        float4 v2 = ((const float4*)g_v2)[roff];
        s3.x += v1.x * v2.x; s3.y += v1.y * v2.y;
        s3.z += v1.z * v2.z; s3.w += v1.w * v2.w;
    }
    float4 dx = make_float4(s3.x * t4.x + t5.x, s3.y * t4.y + t5.y,
                            s3.z * t4.z + t5.z, s3.w * t4.w + t5.w);
    ((float4*)out)[off] = dx;
}

// ---------------- launch ----------------
extern "C" void kernel_launch(void* const* d_in, const int* in_sizes, int n_in,
                              void* d_out, int out_size)
{
    (void)in_sizes; (void)n_in; (void)out_size;
    const int*   node_idx   = (const int*)  d_in[0];
    const int*   group_idx  = (const int*)  d_in[1];
    const float* node_emb   = (const float*)d_in[2];
    const float* node_vec   = (const float*)d_in[3];
    const float* group_emb  = (const float*)d_in[4];
    const float* group_vec  = (const float*)d_in[5];
    const float* edge_attr  = (const float*)d_in[6];
    const float* edge_vec   = (const float*)d_in[8];
    const float* Wq  = (const float*)d_in[9];
    const float* bq  = (const float*)d_in[10];
    const float* Wk  = (const float*)d_in[11];
    const float* bk  = (const float*)d_in[12];
    const float* Wv  = (const float*)d_in[13];
    const float* bv  = (const float*)d_in[14];
    const float* Wp1 = (const float*)d_in[15];
    const float* bp1 = (const float*)d_in[16];
    const float* Wp2 = (const float*)d_in[17];
    const float* bp2 = (const float*)d_in[18];
    const float* Ws1 = (const float*)d_in[19];
    const float* bs1 = (const float*)d_in[20];
    const float* Ws2 = (const float*)d_in[21];
    const float* bs2 = (const float*)d_in[22];
    const float* L0  = (const float*)d_in[23];
    const float* L1  = (const float*)d_in[24];
    const float* L2  = (const float*)d_in[25];
    const float* L3  = (const float*)d_in[26];
    const float* L4  = (const float*)d_in[27];
    const float* L5  = (const float*)d_in[28];
    float* out = (float*)d_out;

    const size_t EDGE_SMEM = (size_t)EDGE_SMEM_FLOATS * sizeof(float);

    cudaFuncSetAttribute(tc_gemm, cudaFuncAttributeMaxDynamicSharedMemorySize, TC_SMEM);
    cudaFuncSetAttribute(edge_kernel, cudaFuncAttributeMaxDynamicSharedMemorySize,
                         (int)EDGE_SMEM);

    float *p_q, *p_k, *p_val, *p_ms, *p_mv, *p_t0, *p_t4, *p_t5, *p_v1, *p_v2;
    int *p_cnt;
    cudaGetSymbolAddress((void**)&p_q,  g_q);
    cudaGetSymbolAddress((void**)&p_k,  g_k);
    cudaGetSymbolAddress((void**)&p_val,g_val);
    cudaGetSymbolAddress((void**)&p_ms, g_ms);
    cudaGetSymbolAddress((void**)&p_mv, g_mv);
    cudaGetSymbolAddress((void**)&p_t0, g_t0);
    cudaGetSymbolAddress((void**)&p_t4, g_t4);
    cudaGetSymbolAddress((void**)&p_t5, g_t5);
    cudaGetSymbolAddress((void**)&p_v1, g_v1);
    cudaGetSymbolAddress((void**)&p_v2, g_v2);
    cudaGetSymbolAddress((void**)&p_cnt, g_cnt);

    float* out_dv = out + (size_t)NN * 128;

    // 1) zero accumulators + sort scratch
    cudaMemsetAsync(p_ms, 0, (size_t)NN * 128 * sizeof(float));
    cudaMemsetAsync(p_mv, 0, (size_t)NN * 384 * sizeof(float));
    cudaMemsetAsync(p_cnt, 0, (size_t)GG * sizeof(int));

    // 2) group-sort the edges (counting sort)
    hist_kernel<<<(EE + 255) / 256, 256>>>(group_idx);
    scan_kernel<<<1, 1024>>>();
    scatter_kernel<<<(EE + 255) / 256, 256>>>(group_idx);

    // 3) pre-convert all 9 dense weights (0=Wq 1=Wk 2=Wv 3=L0 4=L1 5=L2 6=L3 7=L4 8=L5)
    wconv_kernel<<<(9 * 8192 + 255) / 256, 256>>>(Wq, Wk, Wv, L0, L1, L2, L3, L4, L5);

    // 4) projections on tensor cores
    tc_gemm<<<(NN + 127) / 128, 256, TC_SMEM>>>(node_emb, NN,
        0, 0, Wq, bq, p_q,
        -1, 0, nullptr, nullptr, nullptr,
        -1, 0, nullptr, nullptr, nullptr);
    tc_gemm<<<(GG + 127) / 128, 256, TC_SMEM>>>(group_emb, GG,
        1, 0, Wk, bk, p_k,
        2, 0, Wv, bv, p_val,
        -1, 0, nullptr, nullptr, nullptr);

    // 5) per-group layer-1 factorization tables
    pprep_kernel<<<(GG * 512 + 255) / 256, 256>>>(Wp1, Ws1);

    // 6) fused edge pipeline (group-sorted order)
    edge_kernel<<<304, 256, EDGE_SMEM>>>(node_idx, group_idx, edge_attr, edge_vec,
                                         bp1, bs1, Wp2, bp2, Ws2, bs2, group_vec);

    // 7) node-side GEMMs: ms -> t0/t4/t5 ; node_vec -> dv (fused) / v1 / v2
    tc_gemm<<<(NN + 127) / 128, 256, TC_SMEM>>>(p_ms, NN,
        3, 0, L0, nullptr, p_t0,
        7, 0, L4, nullptr, p_t4,
        8, 0, L5, nullptr, p_t5);
    tc_gemm<<<(3 * NN + 127) / 128, 256, TC_SMEM>>>(node_vec, 3 * NN,
        4, 1, L1, nullptr, out_dv,
        5, 0, L2, nullptr, p_v1,
        6, 0, L3, nullptr, p_v2);

    // 8) finalize dx
    finalize_kernel<<<(NN * 32 + 255) / 256, 256>>>(out);
}

// round 10
// speedup vs baseline: 1.0068x; 1.0068x over previous
#include <cuda_runtime.h>
#include <cuda_bf16.h>
#include <math.h>
#include <stdint.h>

#define NN 100000
#define GG 6000
#define EE 400000

// ---------------- scratch (static __device__ — no allocs allowed) ----------------
__device__ float g_q  [NN * 128];
__device__ float g_k  [GG * 128];
__device__ float g_val[GG * 128];
__device__ float g_ms [NN * 128];
__device__ float g_mv [NN * 384];
__device__ float g_t0 [NN * 128];
__device__ float g_t4 [NN * 128];
__device__ float g_t5 [NN * 128];
__device__ float g_v1 [NN * 384];
__device__ float g_v2 [NN * 384];
__device__ float g_Pp [GG * 512];
__device__ float g_Ps [GG * 512];
__device__ uint32_t g_whi[9 * 8192];
__device__ uint32_t g_wlo[9 * 8192];
// group-sort scratch
__device__ int g_cnt [GG];
__device__ int g_cur [GG];
__device__ int g_perm[EE];

__device__ __forceinline__ float silu_f(float x) {
    return x / (1.0f + __expf(-x));
}

// blocked-atom SW128 byte offset for a [128 rows][128 cols bf16] tile
__device__ __forceinline__ uint32_t blk_off(int row, int col) {
    uint32_t off = (uint32_t)((row >> 3) + (col >> 6) * 16) * 1024u
                 + (uint32_t)(row & 7) * 128u + (uint32_t)(col & 63) * 2u;
    return off ^ ((off >> 3) & 0x70);
}

// ---------------- counting sort of edges by group ----------------
__global__ void hist_kernel(const int* __restrict__ gidx) {
    int e = blockIdx.x * 256 + threadIdx.x;
    if (e < EE) atomicAdd(&g_cnt[gidx[e]], 1);
}

__global__ void scan_kernel() {
    __shared__ int part[1024];
    int tid = threadIdx.x;
    int c0 = tid * 6;
    int local[6];
    int s = 0;
    #pragma unroll
    for (int i = 0; i < 6; i++) {
        int v = (c0 + i < GG) ? g_cnt[c0 + i] : 0;
        local[i] = s; s += v;
    }
    part[tid] = s;
    __syncthreads();
    for (int off = 1; off < 1024; off <<= 1) {
        int v = (tid >= off) ? part[tid - off] : 0;
        __syncthreads();
        part[tid] += v;
        __syncthreads();
    }
    int base = (tid > 0) ? part[tid - 1] : 0;
    #pragma unroll
    for (int i = 0; i < 6; i++)
        if (c0 + i < GG) g_cur[c0 + i] = base + local[i];
}

__global__ void scatter_kernel(const int* __restrict__ gidx) {
    int e = blockIdx.x * 256 + threadIdx.x;
    if (e < EE) {
        int pos = atomicAdd(&g_cur[gidx[e]], 1);
        g_perm[pos] = e;
    }
}

// ---------------- weight conversion: W[k][n] fp32 -> B[n][k] bf16 hi/lo ----------------
__global__ void wconv_kernel(
    const float* __restrict__ W0, const float* __restrict__ W1,
    const float* __restrict__ W2, const float* __restrict__ W3,
    const float* __restrict__ W4, const float* __restrict__ W5,
    const float* __restrict__ W6, const float* __restrict__ W7,
    const float* __restrict__ W8)
{
    const float* Ws[9] = {W0, W1, W2, W3, W4, W5, W6, W7, W8};
    int gidx = blockIdx.x * 256 + threadIdx.x;
    if (gidx >= 9 * 8192) return;
    int w = gidx >> 13, p = gidx & 8191;
    int n = p >> 6, k2 = (p & 63) * 2;
    const float* W = Ws[w];
    float x0 = W[k2 * 128 + n], x1 = W[(k2 + 1) * 128 + n];
    __nv_bfloat16 h0 = __float2bfloat16(x0), h1 = __float2bfloat16(x1);
    float r0 = x0 - __bfloat162float(h0), r1 = x1 - __bfloat162float(h1);
    __nv_bfloat16 l0 = __float2bfloat16(r0), l1 = __float2bfloat16(r1);
    uint32_t o = blk_off(n, k2) >> 2;
    g_whi[w * 8192 + o] = (uint32_t)__bfloat16_as_ushort(h0)
                        | ((uint32_t)__bfloat16_as_ushort(h1) << 16);
    g_wlo[w * 8192 + o] = (uint32_t)__bfloat16_as_ushort(l0)
                        | ((uint32_t)__bfloat16_as_ushort(l1) << 16);
}

// ---------------- arch-specific PTX helpers (guarded) ----------------
#if defined(__CUDA_ARCH_FEAT_SM103_ALL) || !defined(__CUDA_ARCH__)
#define HAVE_TCGEN05 1
#else
#define HAVE_TCGEN05 0
#endif

__device__ __forceinline__ uint32_t smem_u32(const void* p) {
    uint32_t a;
    asm("{ .reg .u64 t; cvta.to.shared.u64 t, %1; cvt.u32.u64 %0, t; }"
        : "=r"(a) : "l"(p));
    return a;
}

#if HAVE_TCGEN05
__device__ __forceinline__ uint32_t elect1() {
    uint32_t p;
    asm volatile("{\n\t.reg .pred p;\n\telect.sync _|p, 0xFFFFFFFF;\n\t"
                 "selp.b32 %0, 1, 0, p;\n\t}" : "=r"(p));
    return p;
}
__device__ __forceinline__ void mma_f16_ss(uint32_t d, uint64_t a, uint64_t b,
                                           uint32_t idesc, uint32_t en) {
    asm volatile("{\n\t.reg .pred p;\n\tsetp.ne.u32 p, %5, 0;\n\t"
                 "tcgen05.mma.cta_group::1.kind::f16 [%0], %1, %2, %3, {%4,%4,%4,%4}, p;\n\t}"
                 :: "r"(d), "l"(a), "l"(b), "r"(idesc), "r"(0u), "r"(en) : "memory");
}
__device__ __forceinline__ void mbar_wait(uint32_t mbar, uint32_t parity) {
    uint32_t done;
    asm volatile("{\n\t.reg .pred p;\n\t"
                 "mbarrier.try_wait.parity.acquire.cta.shared::cta.b64 p, [%1], %2;\n\t"
                 "selp.b32 %0, 1, 0, p;\n\t}"
                 : "=r"(done) : "r"(mbar), "r"(parity) : "memory");
    if (!done) {
        asm volatile("{\n\t.reg .pred P1;\n\t"
                     "WAIT_LOOP_%=:\n\t"
                     "mbarrier.try_wait.parity.acquire.cta.shared::cta.b64 P1, [%0], %1, 0x989680;\n\t"
                     "@P1 bra.uni WAIT_DONE_%=;\n\t"
                     "bra.uni WAIT_LOOP_%=;\n\t"
                     "WAIT_DONE_%=:\n\t}"
                     :: "r"(mbar), "r"(parity) : "memory");
    }
}
#define LDTM_X32(r, addr) \
    asm volatile( \
        "tcgen05.ld.sync.aligned.32x32b.x32.b32 " \
        "{%0, %1, %2, %3, %4, %5, %6, %7, " \
        " %8, %9, %10, %11, %12, %13, %14, %15, " \
        " %16, %17, %18, %19, %20, %21, %22, %23, " \
        " %24, %25, %26, %27, %28, %29, %30, %31}, [%32];" \
        : "=r"((r)[0]),  "=r"((r)[1]),  "=r"((r)[2]),  "=r"((r)[3]), \
          "=r"((r)[4]),  "=r"((r)[5]),  "=r"((r)[6]),  "=r"((r)[7]), \
          "=r"((r)[8]),  "=r"((r)[9]),  "=r"((r)[10]), "=r"((r)[11]), \
          "=r"((r)[12]), "=r"((r)[13]), "=r"((r)[14]), "=r"((r)[15]), \
          "=r"((r)[16]), "=r"((r)[17]), "=r"((r)[18]), "=r"((r)[19]), \
          "=r"((r)[20]), "=r"((r)[21]), "=r"((r)[22]), "=r"((r)[23]), \
          "=r"((r)[24]), "=r"((r)[25]), "=r"((r)[26]), "=r"((r)[27]), \
          "=r"((r)[28]), "=r"((r)[29]), "=r"((r)[30]), "=r"((r)[31]) \
        : "r"(addr))
#endif  // HAVE_TCGEN05

// ---------------- pipelined tcgen05 GEMM: up to 3 weights, TMEM ping-pong ----------------
// mode 0: C = A@W (+bias). mode 1: C = g_mv + g_t0[row/3] * (A@W)   (dv fusion)
#define SM_TMEM 0
#define SM_MB0  8
#define SM_MB1  16
#define SM_MB2  24
#define SM_AHI  1024
#define SM_ALO  33792
#define SM_B0HI 66560
#define SM_B0LO 99328
#define SM_B1HI 132096
#define SM_B1LO 164864
#define TC_SMEM 197632
#define TMEM_COLS 512

#if HAVE_TCGEN05
__device__ __forceinline__ void tc_copyB(char* smem, uint32_t dsthi, uint32_t dstlo,
                                         int w, int tid)
{
    const uint4* shi = (const uint4*)(g_whi + w * 8192);
    const uint4* slo = (const uint4*)(g_wlo + w * 8192);
    uint4* dhi = (uint4*)(smem + dsthi);
    uint4* dlo = (uint4*)(smem + dstlo);
    for (int i = tid; i < 2048; i += 256) { dhi[i] = shi[i]; dlo[i] = slo[i]; }
}

__device__ __forceinline__ void tc_issue_mma(uint32_t tmem_d, uint64_t ahi, uint64_t alo,
                                             uint64_t bhi, uint64_t blo, uint32_t mbar)
{
    const uint32_t IDESC = (1u << 4) | (1u << 7) | (1u << 10) | (16u << 17) | (8u << 24);
    uint32_t en = 0;
    #pragma unroll
    for (int kc = 0; kc < 8; kc++) {
        uint64_t ko = (uint64_t)((kc & 3) * 2 + (kc >> 2) * 1024);
        mma_f16_ss(tmem_d, ahi + ko, bhi + ko, IDESC, en); en = 1;
    }
    #pragma unroll
    for (int kc = 0; kc < 8; kc++) {
        uint64_t ko = (uint64_t)((kc & 3) * 2 + (kc >> 2) * 1024);
        mma_f16_ss(tmem_d, ahi + ko, blo + ko, IDESC, 1);
    }
    #pragma unroll
    for (int kc = 0; kc < 8; kc++) {
        uint64_t ko = (uint64_t)((kc & 3) * 2 + (kc >> 2) * 1024);
        mma_f16_ss(tmem_d, alo + ko, bhi + ko, IDESC, 1);
    }
    asm volatile("tcgen05.commit.cta_group::1.mbarrier::arrive::one.shared::cluster.b64 [%0];"
                 :: "r"(mbar) : "memory");
}

__device__ __forceinline__ void tc_epilogue(uint32_t tmem_d, int M, int row0,
                                            int wid, int lane, int mode,
                                            const float* bias, float* C)
{
    if (wid >= 4) return;
    int gr = row0 + wid * 32 + lane;
    #pragma unroll 1
    for (int cb = 0; cb < 4; cb++) {
        uint32_t d[32];
        LDTM_X32(d, tmem_d + cb * 32);
        asm volatile("tcgen05.wait::ld.sync.aligned;" ::: "memory");
        if (gr < M) {
            float* dst = C + (size_t)gr * 128 + cb * 32;
            if (mode == 1) {
                const float4* mvp = (const float4*)(g_mv + (size_t)gr * 128 + cb * 32);
                const float4* t0p = (const float4*)(g_t0 + (size_t)(gr / 3) * 128 + cb * 32);
                #pragma unroll
                for (int q = 0; q < 8; q++) {
                    float4 mv = mvp[q], t0 = t0p[q];
                    float4 o;
                    o.x = mv.x + t0.x * __uint_as_float(d[q * 4 + 0]);
                    o.y = mv.y + t0.y * __uint_as_float(d[q * 4 + 1]);
                    o.z = mv.z + t0.z * __uint_as_float(d[q * 4 + 2]);
                    o.w = mv.w + t0.w * __uint_as_float(d[q * 4 + 3]);
                    ((float4*)dst)[q] = o;
                }
            } else {
                #pragma unroll
                for (int q = 0; q < 8; q++) {
                    float4 o;
                    o.x = __uint_as_float(d[q * 4 + 0]);
                    o.y = __uint_as_float(d[q * 4 + 1]);
                    o.z = __uint_as_float(d[q * 4 + 2]);
                    o.w = __uint_as_float(d[q * 4 + 3]);
                    if (bias) {
                        const float* bb = bias + cb * 32 + q * 4;
                        o.x += bb[0]; o.y += bb[1]; o.z += bb[2]; o.w += bb[3];
                    }
                    ((float4*)dst)[q] = o;
                }
            }
        }
    }
}
#endif  // HAVE_TCGEN05

__global__ __launch_bounds__(256, 1) __cluster_dims__(1, 1, 1)
void tc_gemm(const float* __restrict__ A, int M,
             int w0, int m0, const float* __restrict__ W0f, const float* __restrict__ b0, float* __restrict__ C0,
             int w1, int m1, const float* __restrict__ W1f, const float* __restrict__ b1, float* __restrict__ C1,
             int w2, int m2, const float* __restrict__ W2f, const float* __restrict__ b2, float* __restrict__ C2)
{
#if HAVE_TCGEN05
    extern __shared__ char smem[];
    uint32_t sb = smem_u32(smem);
    int tid = threadIdx.x, wid = tid >> 5, lane = tid & 31;
    int row0 = blockIdx.x * 128;

    if (wid == 0)
        asm volatile("tcgen05.alloc.cta_group::1.sync.aligned.shared::cta.b32 [%0], %1;"
                     :: "r"(sb + SM_TMEM), "r"((uint32_t)TMEM_COLS) : "memory");
    if (tid == 0) {
        asm volatile("mbarrier.init.shared.b64 [%0], 1;" :: "r"(sb + SM_MB0) : "memory");
        asm volatile("mbarrier.init.shared.b64 [%0], 1;" :: "r"(sb + SM_MB1) : "memory");
        asm volatile("mbarrier.init.shared.b64 [%0], 1;" :: "r"(sb + SM_MB2) : "memory");
    }
    __syncthreads();
    uint32_t tmem;
    asm volatile("ld.shared.b32 %0, [%1];" : "=r"(tmem) : "r"(sb + SM_TMEM));

    for (int p = tid; p < 8192; p += 256) {
        int r = p >> 6, k2 = (p & 63) * 2;
        float2 x = make_float2(0.f, 0.f);
        if (row0 + r < M) x = *(const float2*)(A + (size_t)(row0 + r) * 128 + k2);
        __nv_bfloat16 h0 = __float2bfloat16(x.x), h1 = __float2bfloat16(x.y);
        float r0f = x.x - __bfloat162float(h0), r1f = x.y - __bfloat162float(h1);
        __nv_bfloat16 l0 = __float2bfloat16(r0f), l1 = __float2bfloat16(r1f);
        uint32_t hiw = (uint32_t)__bfloat16_as_ushort(h0)
                     | ((uint32_t)__bfloat16_as_ushort(h1) << 16);
        uint32_t low = (uint32_t)__bfloat16_as_ushort(l0)
                     | ((uint32_t)__bfloat16_as_ushort(l1) << 16);
        uint32_t off = blk_off(r, k2);
        *(uint32_t*)(smem + SM_AHI + off) = hiw;
        *(uint32_t*)(smem + SM_ALO + off) = low;
    }

    const uint64_t DESCB = (2ull << 61) | (1ull << 46) | (64ull << 32) | (1ull << 16);
    uint64_t ahi  = DESCB | ((uint64_t)((sb + SM_AHI)  >> 4) & 0x3FFF);
    uint64_t alo  = DESCB | ((uint64_t)((sb + SM_ALO)  >> 4) & 0x3FFF);
    uint64_t b0hi = DESCB | ((uint64_t)((sb + SM_B0HI) >> 4) & 0x3FFF);
    uint64_t b0lo = DESCB | ((uint64_t)((sb + SM_B0LO) >> 4) & 0x3FFF);
    uint64_t b1hi = DESCB | ((uint64_t)((sb + SM_B1HI) >> 4) & 0x3FFF);
    uint64_t b1lo = DESCB | ((uint64_t)((sb + SM_B1LO) >> 4) & 0x3FFF);

    tc_copyB(smem, SM_B0HI, SM_B0LO, w0, tid);
    asm volatile("fence.proxy.async.shared::cta;" ::: "memory");
    __syncthreads();
    if (wid == 0 && elect1())
        tc_issue_mma(tmem, ahi, alo, b0hi, b0lo, sb + SM_MB0);

    if (w1 >= 0) {
        tc_copyB(smem, SM_B1HI, SM_B1LO, w1, tid);
        asm volatile("fence.proxy.async.shared::cta;" ::: "memory");
        __syncthreads();
        if (wid == 0 && elect1())
            tc_issue_mma(tmem + 128, ahi, alo, b1hi, b1lo, sb + SM_MB1);
    }

    mbar_wait(sb + SM_MB0, 0);
    asm volatile("tcgen05.fence::after_thread_sync;" ::: "memory");
    if (w2 >= 0) {
        tc_copyB(smem, SM_B0HI, SM_B0LO, w2, tid);
        asm volatile("fence.proxy.async.shared::cta;" ::: "memory");
        __syncthreads();
        if (wid == 0 && elect1())
            tc_issue_mma(tmem + 256, ahi, alo, b0hi, b0lo, sb + SM_MB2);
    }

    tc_epilogue(tmem, M, row0, wid, lane, m0, b0, C0);
    if (w1 >= 0) {
        mbar_wait(sb + SM_MB1, 0);
        asm volatile("tcgen05.fence::after_thread_sync;" ::: "memory");
        tc_epilogue(tmem + 128, M, row0, wid, lane, m1, b1, C1);
    }
    if (w2 >= 0) {
        mbar_wait(sb + SM_MB2, 0);
        asm volatile("tcgen05.fence::after_thread_sync;" ::: "memory");
        tc_epilogue(tmem + 256, M, row0, wid, lane, m2, b2, C2);
    }
    asm volatile("tcgen05.fence::before_thread_sync;" ::: "memory");
    __syncthreads();

    if (tid == 0) {
        asm volatile("mbarrier.inval.shared.b64 [%0];" :: "r"(sb + SM_MB0) : "memory");
        asm volatile("mbarrier.inval.shared.b64 [%0];" :: "r"(sb + SM_MB1) : "memory");
        asm volatile("mbarrier.inval.shared.b64 [%0];" :: "r"(sb + SM_MB2) : "memory");
    }
    __syncthreads();
    if (wid == 0)
        asm volatile("tcgen05.dealloc.cta_group::1.sync.aligned.b32 %0, %1;"
                     :: "r"(tmem), "r"((uint32_t)TMEM_COLS));

#else  // ---------------- SIMT fp32 fallback (plain sm_103 pass) ----------------
    extern __shared__ float smf[];
    float* sA = smf;
    float* sW = smf + 16384;
    int tid = threadIdx.x;
    int row0 = blockIdx.x * 128;

    for (int i = tid; i < 4096; i += 256) {
        int r  = i >> 5;
        int gr = row0 + r;
        float4 v = make_float4(0.f, 0.f, 0.f, 0.f);
        if (gr < M) v = ((const float4*)A)[(size_t)gr * 32 + (i & 31)];
        ((float4*)sA)[i] = v;
    }

    const float* Wf[3] = {W0f, W1f, W2f};
    const float* bpf[3] = {b0, b1, b2};
    float* cpf[3] = {C0, C1, C2};
    int widxf[3] = {w0, w1, w2};
    int modef[3] = {m0, m1, m2};

    #pragma unroll 1
    for (int j = 0; j < 3; j++) {
        if (widxf[j] < 0) break;
        __syncthreads();
        for (int i = tid; i < 4096; i += 256)
            ((float4*)sW)[i] = ((const float4*)Wf[j])[i];
        __syncthreads();

        int rb = tid >> 4, cb = tid & 15;
        float acc[8][8];
        #pragma unroll
        for (int i = 0; i < 8; i++)
            #pragma unroll
            for (int q = 0; q < 8; q++) acc[i][q] = 0.f;

        #pragma unroll 4
        for (int k = 0; k < 128; k++) {
            float4 wv0 = *(const float4*)&sW[k * 128 + cb * 8];
            float4 wv1 = *(const float4*)&sW[k * 128 + cb * 8 + 4];
            float w[8] = {wv0.x, wv0.y, wv0.z, wv0.w, wv1.x, wv1.y, wv1.z, wv1.w};
            float a[8];
            #pragma unroll
            for (int i = 0; i < 8; i++) a[i] = sA[(rb * 8 + i) * 128 + k];
            #pragma unroll
            for (int i = 0; i < 8; i++)
                #pragma unroll
                for (int q = 0; q < 8; q++) acc[i][q] += a[i] * w[q];
        }

        #pragma unroll
        for (int i = 0; i < 8; i++) {
            int gr = row0 + rb * 8 + i;
            if (gr < M) {
                float* dst = cpf[j] + (size_t)gr * 128 + cb * 8;
                for (int q = 0; q < 8; q++) {
                    float o = acc[i][q];
                    if (modef[j] == 1)
                        o = g_mv[(size_t)gr * 128 + cb * 8 + q]
                          + g_t0[(size_t)(gr / 3) * 128 + cb * 8 + q] * o;
                    else if (bpf[j]) o += bpf[j][cb * 8 + q];
                    dst[q] = o;
                }
            }
        }
    }
#endif
}

// ---------------- P precompute ----------------
__global__ void pprep_kernel(const float* __restrict__ Wp1,
                             const float* __restrict__ Ws1)
{
    int idx = blockIdx.x * blockDim.x + threadIdx.x;
    if (idx >= GG * 512) return;
    int g  = idx >> 9;
    int hc = idx & 511;
    int h  = hc >> 6, c = hc & 63;
    const float* vp = g_val + (size_t)g * 128 + h * 16;
    float sp = 0.f, ss = 0.f;
    #pragma unroll
    for (int i = 0; i < 16; i++) {
        float v = vp[i];
        int wrow = (h * 16 + i) * 64 + c;
        sp += v * Wp1[wrow];
        ss += v * Ws1[wrow];
    }
    g_Pp[idx] = sp;
    g_Ps[idx] = ss;
}

// ---------------- fused edge kernel (group-sorted via g_perm) ----------------
#define EO_WP2  0
#define EO_WS2  8192
#define EO_HP   16384
#define EO_HS   20480
#define EO_ATT  24576
#define EO_BP1  25088
#define EO_BS1  25152
#define EO_BP2  25216
#define EO_BS2  25344
#define EO_U    25472
#define EO_N    25664
#define EO_G    25728
#define EO_E    25792
#define EDGE_SMEM_FLOATS 25856

__global__ __launch_bounds__(256, 2) void edge_kernel(
    const int*   __restrict__ node_idx,
    const int*   __restrict__ group_idx,
    const float* __restrict__ edge_attr,
    const float* __restrict__ edge_vec,
    const float* __restrict__ bp1, const float* __restrict__ bs1,
    const float* __restrict__ Wp2, const float* __restrict__ bp2,
    const float* __restrict__ Ws2, const float* __restrict__ bs2,
    const float* __restrict__ gvec)
{
    extern __shared__ float sm[];
    float* sWp2  = sm + EO_WP2;
    float* sWs2  = sm + EO_WS2;
    float* s_hp  = sm + EO_HP;
    float* s_hs  = sm + EO_HS;
    float* s_attn= sm + EO_ATT;
    float* s_bp1 = sm + EO_BP1;
    float* s_bs1 = sm + EO_BS1;
    float* s_bp2 = sm + EO_BP2;
    float* s_bs2 = sm + EO_BS2;
    float* s_u   = sm + EO_U;
    int*   s_n   = (int*)(sm + EO_N);
    int*   s_g   = (int*)(sm + EO_G);
    int*   s_e   = (int*)(sm + EO_E);

    int tid = threadIdx.x;

    for (int i = tid; i < 2048; i += 256) {
        ((float4*)sWp2)[i] = ((const float4*)Wp2)[i];
        ((float4*)sWs2)[i] = ((const float4*)Ws2)[i];
    }
    if (tid < 64)  { s_bp1[tid] = bp1[tid]; s_bs1[tid] = bs1[tid]; }
    if (tid < 128) { s_bp2[tid] = bp2[tid]; s_bs2[tid] = bs2[tid]; }
    __syncthreads();

    const int ntiles = EE / 64;
    for (int t = blockIdx.x; t < ntiles; t += gridDim.x) {
        int e0 = t * 64;

        if (tid < 64) {
            int e = g_perm[e0 + tid];          // group-sorted order
            s_e[tid] = e;
            s_n[tid] = node_idx[e];
            s_g[tid] = group_idx[e];
            s_u[tid * 3 + 0] = -edge_vec[e * 3 + 0];
            s_u[tid * 3 + 1] = -edge_vec[e * 3 + 1];
            s_u[tid * 3 + 2] = -edge_vec[e * 3 + 2];
        }
        __syncthreads();

        #pragma unroll
        for (int p = tid; p < 512; p += 256) {
            int le = p >> 3, h = p & 7;
            const float4* qp = (const float4*)(g_q + (size_t)s_n[le] * 128 + h * 16);
            const float4* kp = (const float4*)(g_k + (size_t)s_g[le] * 128 + h * 16);
            const float4* ep = (const float4*)(edge_attr + (size_t)s_e[le] * 128 + h * 16);
            float dot = 0.f;
            #pragma unroll
            for (int c = 0; c < 4; c++) {
                float4 qv = qp[c], kv = kp[c], ev = ep[c];
                dot += qv.x * kv.x * ev.x + qv.y * kv.y * ev.y
                     + qv.z * kv.z * ev.z + qv.w * kv.w * ev.w;
            }
            s_attn[le * 8 + h] = silu_f(dot * 0.25f);
        }
        __syncthreads();

        for (int i4 = tid; i4 < 2048; i4 += 256) {
            int le = i4 >> 5, j4 = i4 & 31;
            float4 v = ((const float4*)(g_val + (size_t)s_g[le] * 128))[j4];
            float  a = s_attn[le * 8 + (j4 >> 2)];
            float4 m = make_float4(v.x * a, v.y * a, v.z * a, v.w * a);
            atomicAdd((float4*)(g_ms + (size_t)s_n[le] * 128 + j4 * 4), m);
        }

        {
            int le = tid >> 2, cq = tid & 3, c0 = cq * 16;
            int g = s_g[le];
            float at[8];
            #pragma unroll
            for (int h = 0; h < 8; h++) at[h] = s_attn[le * 8 + h];
            float hp[16], hs[16];
            #pragma unroll
            for (int j = 0; j < 16; j++) { hp[j] = 0.f; hs[j] = 0.f; }
            const float4* Pp4 = (const float4*)(g_Pp + (size_t)g * 512);
            const float4* Ps4 = (const float4*)(g_Ps + (size_t)g * 512);
            #pragma unroll
            for (int h = 0; h < 8; h++) {
                int base = h * 16 + cq * 4;
                float ah = at[h];
                #pragma unroll
                for (int q = 0; q < 4; q++) {
                    float4 p = Pp4[base + q];
                    float4 s = Ps4[base + q];
                    hp[q*4+0] += ah * p.x; hp[q*4+1] += ah * p.y;
                    hp[q*4+2] += ah * p.z; hp[q*4+3] += ah * p.w;
                    hs[q*4+0] += ah * s.x; hs[q*4+1] += ah * s.y;
                    hs[q*4+2] += ah * s.z; hs[q*4+3] += ah * s.w;
                }
            }
            #pragma unroll
            for (int j = 0; j < 16; j++) {
                s_hp[le * 64 + c0 + j] = silu_f(hp[j] + s_bp1[c0 + j]);
                s_hs[le * 64 + c0 + j] = silu_f(hs[j] + s_bs1[c0 + j]);
            }
        }
        __syncthreads();

        {
            int rg = tid >> 4, cg = tid & 15;
            float sp[4][8], sv[4][8];
            #pragma unroll
            for (int i = 0; i < 4; i++)
                #pragma unroll
                for (int j = 0; j < 8; j++) { sp[i][j] = 0.f; sv[i][j] = 0.f; }

            #pragma unroll 2
            for (int k = 0; k < 64; k++) {
                float hp[4], hs[4];
                #pragma unroll
                for (int i = 0; i < 4; i++) {
                    hp[i] = s_hp[(rg * 4 + i) * 64 + k];
                    hs[i] = s_hs[(rg * 4 + i) * 64 + k];
                }
                float4 wpa = *(const float4*)&sWp2[k * 128 + cg * 8];
                float4 wpb = *(const float4*)&sWp2[k * 128 + cg * 8 + 4];
                float4 wsa = *(const float4*)&sWs2[k * 128 + cg * 8];
                float4 wsb = *(const float4*)&sWs2[k * 128 + cg * 8 + 4];
                float wp[8] = {wpa.x, wpa.y, wpa.z, wpa.w, wpb.x, wpb.y, wpb.z, wpb.w};
                float ws[8] = {wsa.x, wsa.y, wsa.z, wsa.w, wsb.x, wsb.y, wsb.z, wsb.w};
                #pragma unroll
                for (int i = 0; i < 4; i++)
                    #pragma unroll
                    for (int j = 0; j < 8; j++) {
                        sp[i][j] += hp[i] * wp[j];
                        sv[i][j] += hs[i] * ws[j];
                    }
            }

            float bp[8], bs[8];
            #pragma unroll
            for (int j = 0; j < 8; j++) { bp[j] = s_bp2[cg * 8 + j]; bs[j] = s_bs2[cg * 8 + j]; }

            #pragma unroll
            for (int i = 0; i < 4; i++) {
                int le = rg * 4 + i;
                int n = s_n[le], g = s_g[le];
                float spv[8], svv[8];
                #pragma unroll
                for (int j = 0; j < 8; j++) { spv[j] = sp[i][j] + bp[j]; svv[j] = sv[i][j] + bs[j]; }
                #pragma unroll
                for (int d = 0; d < 3; d++) {
                    float ud = s_u[le * 3 + d];
                    const float* gv = gvec + (size_t)g * 384 + d * 128 + cg * 8;
                    float4 g0 = *(const float4*)gv;
                    float4 g1 = *(const float4*)(gv + 4);
                    float4 o0 = make_float4(spv[0] * ud + svv[0] * g0.x,
                                            spv[1] * ud + svv[1] * g0.y,
                                            spv[2] * ud + svv[2] * g0.z,
                                            spv[3] * ud + svv[3] * g0.w);
                    float4 o1 = make_float4(spv[4] * ud + svv[4] * g1.x,
                                            spv[5] * ud + svv[5] * g1.y,
                                            spv[6] * ud + svv[6] * g1.z,
                                            spv[7] * ud + svv[7] * g1.w);
                    float* dst = g_mv + (size_t)n * 384 + d * 128 + cg * 8;
                    atomicAdd((float4*)dst, o0);
                    atomicAdd((float4*)(dst + 4), o1);
                }
            }
        }
        __syncthreads();
    }
}

// ---------------- finalize: dx only (dv fused into tc_gemm epilogue) ----------------
__global__ void finalize_kernel(float* __restrict__ out) {
    int idx = blockIdx.x * blockDim.x + threadIdx.x;
    if (idx >= NN * 32) return;
    int n = idx >> 5, j4 = idx & 31;
    size_t off = (size_t)n * 32 + j4;
    float4 t4 = ((const float4*)g_t4)[off];
    float4 t5 = ((const float4*)g_t5)[off];
    float4 s3 = make_float4(0.f, 0.f, 0.f, 0.f);
    #pragma unroll
    for (int d = 0; d < 3; d++) {
        size_t roff = ((size_t)n * 3 + d) * 32 + j4;
        float4 v1 = ((const float4*)g_v1)[roff];
        float4 v2 = ((const float4*)g_v2)[roff];
        s3.x += v1.x * v2.x; s3.y += v1.y * v2.y;
        s3.z += v1.z * v2.z; s3.w += v1.w * v2.w;
    }
    float4 dx = make_float4(s3.x * t4.x + t5.x, s3.y * t4.y + t5.y,
                            s3.z * t4.z + t5.z, s3.w * t4.w + t5.w);
    ((float4*)out)[off] = dx;
}

// ---------------- launch ----------------
extern "C" void kernel_launch(void* const* d_in, const int* in_sizes, int n_in,
                              void* d_out, int out_size)
{
    (void)in_sizes; (void)n_in; (void)out_size;
    const int*   node_idx   = (const int*)  d_in[0];
    const int*   group_idx  = (const int*)  d_in[1];
    const float* node_emb   = (const float*)d_in[2];
    const float* node_vec   = (const float*)d_in[3];
    const float* group_emb  = (const float*)d_in[4];
    const float* group_vec  = (const float*)d_in[5];
    const float* edge_attr  = (const float*)d_in[6];
    const float* edge_vec   = (const float*)d_in[8];
    const float* Wq  = (const float*)d_in[9];
    const float* bq  = (const float*)d_in[10];
    const float* Wk  = (const float*)d_in[11];
    const float* bk  = (const float*)d_in[12];
    const float* Wv  = (const float*)d_in[13];
    const float* bv  = (const float*)d_in[14];
    const float* Wp1 = (const float*)d_in[15];
    const float* bp1 = (const float*)d_in[16];
    const float* Wp2 = (const float*)d_in[17];
    const float* bp2 = (const float*)d_in[18];
    const float* Ws1 = (const float*)d_in[19];
    const float* bs1 = (const float*)d_in[20];
    const float* Ws2 = (const float*)d_in[21];
    const float* bs2 = (const float*)d_in[22];
    const float* L0  = (const float*)d_in[23];
    const float* L1  = (const float*)d_in[24];
    const float* L2  = (const float*)d_in[25];
    const float* L3  = (const float*)d_in[26];
    const float* L4  = (const float*)d_in[27];
    const float* L5  = (const float*)d_in[28];
    float* out = (float*)d_out;

    const size_t EDGE_SMEM = (size_t)EDGE_SMEM_FLOATS * sizeof(float);

    cudaFuncSetAttribute(tc_gemm, cudaFuncAttributeMaxDynamicSharedMemorySize, TC_SMEM);
    cudaFuncSetAttribute(edge_kernel, cudaFuncAttributeMaxDynamicSharedMemorySize,
                         (int)EDGE_SMEM);

    float *p_q, *p_k, *p_val, *p_ms, *p_mv, *p_t0, *p_t4, *p_t5, *p_v1, *p_v2;
    int *p_cnt;
    cudaGetSymbolAddress((void**)&p_q,  g_q);
    cudaGetSymbolAddress((void**)&p_k,  g_k);
    cudaGetSymbolAddress((void**)&p_val,g_val);
    cudaGetSymbolAddress((void**)&p_ms, g_ms);
    cudaGetSymbolAddress((void**)&p_mv, g_mv);
    cudaGetSymbolAddress((void**)&p_t0, g_t0);
    cudaGetSymbolAddress((void**)&p_t4, g_t4);
    cudaGetSymbolAddress((void**)&p_t5, g_t5);
    cudaGetSymbolAddress((void**)&p_v1, g_v1);
    cudaGetSymbolAddress((void**)&p_v2, g_v2);
    cudaGetSymbolAddress((void**)&p_cnt, g_cnt);

    float* out_dv = out + (size_t)NN * 128;

    // 1) zero accumulators + sort scratch
    cudaMemsetAsync(p_ms, 0, (size_t)NN * 128 * sizeof(float));
    cudaMemsetAsync(p_mv, 0, (size_t)NN * 384 * sizeof(float));
    cudaMemsetAsync(p_cnt, 0, (size_t)GG * sizeof(int));

    // 2) group-sort the edges (counting sort)
    hist_kernel<<<(EE + 255) / 256, 256>>>(group_idx);
    scan_kernel<<<1, 1024>>>();
    scatter_kernel<<<(EE + 255) / 256, 256>>>(group_idx);

    // 3) pre-convert all 9 dense weights (0=Wq 1=Wk 2=Wv 3=L0 4=L1 5=L2 6=L3 7=L4 8=L5)
    wconv_kernel<<<(9 * 8192 + 255) / 256, 256>>>(Wq, Wk, Wv, L0, L1, L2, L3, L4, L5);

    // 4) projections on tensor cores
    tc_gemm<<<(NN + 127) / 128, 256, TC_SMEM>>>(node_emb, NN,
        0, 0, Wq, bq, p_q,
        -1, 0, nullptr, nullptr, nullptr,
        -1, 0, nullptr, nullptr, nullptr);
    tc_gemm<<<(GG + 127) / 128, 256, TC_SMEM>>>(group_emb, GG,
        1, 0, Wk, bk, p_k,
        2, 0, Wv, bv, p_val,
        -1, 0, nullptr, nullptr, nullptr);

    // 5) per-group layer-1 factorization tables
    pprep_kernel<<<(GG * 512 + 255) / 256, 256>>>(Wp1, Ws1);

    // 6) fused edge pipeline (group-sorted order)
    edge_kernel<<<304, 256, EDGE_SMEM>>>(node_idx, group_idx, edge_attr, edge_vec,
                                         bp1, bs1, Wp2, bp2, Ws2, bs2, group_vec);

    // 7) node-side GEMMs: ms -> t0/t4/t5 ; node_vec -> dv (fused) / v1 / v2
    tc_gemm<<<(NN + 127) / 128, 256, TC_SMEM>>>(p_ms, NN,
        3, 0, L0, nullptr, p_t0,
        7, 0, L4, nullptr, p_t4,
        8, 0, L5, nullptr, p_t5);
    tc_gemm<<<(3 * NN + 127) / 128, 256, TC_SMEM>>>(node_vec, 3 * NN,
        4, 1, L1, nullptr, out_dv,
        5, 0, L2, nullptr, p_v1,
        6, 0, L3, nullptr, p_v2);

    // 8) finalize dx
    finalize_kernel<<<(NN * 32 + 255) / 256, 256>>>(out);
}

// round 11
// speedup vs baseline: 1.0901x; 1.0827x over previous
#include <cuda_runtime.h>
#include <cuda_bf16.h>
#include <math.h>
#include <stdint.h>

#define NN 100000
#define GG 6000
#define EE 400000

// ---------------- scratch (static __device__ — no allocs allowed) ----------------
__device__ float g_q  [NN * 128];
__device__ float g_k  [GG * 128];
__device__ float g_val[GG * 128];
__device__ float g_ms [NN * 128];
__device__ float g_mv [NN * 384];
__device__ float g_t0 [NN * 128];
__device__ float g_t4 [NN * 128];
__device__ float g_t5 [NN * 128];
__device__ float g_v1 [NN * 384];
__device__ float g_v2 [NN * 384];
__device__ float g_Pp [GG * 512];
__device__ float g_Ps [GG * 512];
__device__ uint32_t g_whi[9 * 8192];
__device__ uint32_t g_wlo[9 * 8192];
__device__ uint32_t g_w2hi[2 * 4096];   // Wp2/Ws2 as B[n=128][k=64] bf16 hi
__device__ uint32_t g_w2lo[2 * 4096];   // ... lo
// group-sort scratch
__device__ int g_cnt [GG];
__device__ int g_cur [GG];
__device__ int g_perm[EE];

__device__ __forceinline__ float silu_f(float x) {
    return x / (1.0f + __expf(-x));
}

// blocked-atom SW128 byte offset for [128 rows][128 cols bf16]
__device__ __forceinline__ uint32_t blk_off(int row, int col) {
    uint32_t off = (uint32_t)((row >> 3) + (col >> 6) * 16) * 1024u
                 + (uint32_t)(row & 7) * 128u + (uint32_t)(col & 63) * 2u;
    return off ^ ((off >> 3) & 0x70);
}
// blocked-atom SW128 byte offset for [128 rows][64 cols bf16] (K=64 tiles)
__device__ __forceinline__ uint32_t blk64_off(int row, int col) {
    uint32_t off = (uint32_t)(row >> 3) * 1024u
                 + (uint32_t)(row & 7) * 128u + (uint32_t)col * 2u;
    return off ^ ((off >> 3) & 0x70);
}

// ---------------- counting sort of edges by group ----------------
__global__ void hist_kernel(const int* __restrict__ gidx) {
    int e = blockIdx.x * 256 + threadIdx.x;
    if (e < EE) atomicAdd(&g_cnt[gidx[e]], 1);
}

__global__ void scan_kernel() {
    __shared__ int part[1024];
    int tid = threadIdx.x;
    int c0 = tid * 6;
    int local[6];
    int s = 0;
    #pragma unroll
    for (int i = 0; i < 6; i++) {
        int v = (c0 + i < GG) ? g_cnt[c0 + i] : 0;
        local[i] = s; s += v;
    }
    part[tid] = s;
    __syncthreads();
    for (int off = 1; off < 1024; off <<= 1) {
        int v = (tid >= off) ? part[tid - off] : 0;
        __syncthreads();
        part[tid] += v;
        __syncthreads();
    }
    int base = (tid > 0) ? part[tid - 1] : 0;
    #pragma unroll
    for (int i = 0; i < 6; i++)
        if (c0 + i < GG) g_cur[c0 + i] = base + local[i];
}

__global__ void scatter_kernel(const int* __restrict__ gidx) {
    int e = blockIdx.x * 256 + threadIdx.x;
    if (e < EE) {
        int pos = atomicAdd(&g_cur[gidx[e]], 1);
        g_perm[pos] = e;
    }
}

// ---------------- weight conversion: W[k][n] fp32 -> B[n][k] bf16 hi/lo ----------------
__global__ void wconv_kernel(
    const float* __restrict__ W0, const float* __restrict__ W1,
    const float* __restrict__ W2, const float* __restrict__ W3,
    const float* __restrict__ W4, const float* __restrict__ W5,
    const float* __restrict__ W6, const float* __restrict__ W7,
    const float* __restrict__ W8)
{
    const float* Ws[9] = {W0, W1, W2, W3, W4, W5, W6, W7, W8};
    int gidx = blockIdx.x * 256 + threadIdx.x;
    if (gidx >= 9 * 8192) return;
    int w = gidx >> 13, p = gidx & 8191;
    int n = p >> 6, k2 = (p & 63) * 2;
    const float* W = Ws[w];
    float x0 = W[k2 * 128 + n], x1 = W[(k2 + 1) * 128 + n];
    __nv_bfloat16 h0 = __float2bfloat16(x0), h1 = __float2bfloat16(x1);
    float r0 = x0 - __bfloat162float(h0), r1 = x1 - __bfloat162float(h1);
    __nv_bfloat16 l0 = __float2bfloat16(r0), l1 = __float2bfloat16(r1);
    uint32_t o = blk_off(n, k2) >> 2;
    g_whi[w * 8192 + o] = (uint32_t)__bfloat16_as_ushort(h0)
                        | ((uint32_t)__bfloat16_as_ushort(h1) << 16);
    g_wlo[w * 8192 + o] = (uint32_t)__bfloat16_as_ushort(l0)
                        | ((uint32_t)__bfloat16_as_ushort(l1) << 16);
}

// Wp2/Ws2 [64 k][128 n] fp32 -> B[n=128][k=64] bf16 hi/lo (blocked K=64)
__global__ void wconv2_kernel(const float* __restrict__ Wp2,
                              const float* __restrict__ Ws2)
{
    int gidx = blockIdx.x * 256 + threadIdx.x;
    if (gidx >= 2 * 4096) return;
    int w = gidx >> 12, p = gidx & 4095;
    int n = p >> 5, k2 = (p & 31) * 2;
    const float* W = w ? Ws2 : Wp2;
    float x0 = W[k2 * 128 + n], x1 = W[(k2 + 1) * 128 + n];
    __nv_bfloat16 h0 = __float2bfloat16(x0), h1 = __float2bfloat16(x1);
    float r0 = x0 - __bfloat162float(h0), r1 = x1 - __bfloat162float(h1);
    __nv_bfloat16 l0 = __float2bfloat16(r0), l1 = __float2bfloat16(r1);
    uint32_t o = blk64_off(n, k2) >> 2;
    g_w2hi[w * 4096 + o] = (uint32_t)__bfloat16_as_ushort(h0)
                         | ((uint32_t)__bfloat16_as_ushort(h1) << 16);
    g_w2lo[w * 4096 + o] = (uint32_t)__bfloat16_as_ushort(l0)
                         | ((uint32_t)__bfloat16_as_ushort(l1) << 16);
}

// ---------------- arch-specific PTX helpers (guarded) ----------------
#if defined(__CUDA_ARCH_FEAT_SM103_ALL) || !defined(__CUDA_ARCH__)
#define HAVE_TCGEN05 1
#else
#define HAVE_TCGEN05 0
#endif

__device__ __forceinline__ uint32_t smem_u32(const void* p) {
    uint32_t a;
    asm("{ .reg .u64 t; cvta.to.shared.u64 t, %1; cvt.u32.u64 %0, t; }"
        : "=r"(a) : "l"(p));
    return a;
}

#if HAVE_TCGEN05
__device__ __forceinline__ uint32_t elect1() {
    uint32_t p;
    asm volatile("{\n\t.reg .pred p;\n\telect.sync _|p, 0xFFFFFFFF;\n\t"
                 "selp.b32 %0, 1, 0, p;\n\t}" : "=r"(p));
    return p;
}
__device__ __forceinline__ void mma_f16_ss(uint32_t d, uint64_t a, uint64_t b,
                                           uint32_t idesc, uint32_t en) {
    asm volatile("{\n\t.reg .pred p;\n\tsetp.ne.u32 p, %5, 0;\n\t"
                 "tcgen05.mma.cta_group::1.kind::f16 [%0], %1, %2, %3, {%4,%4,%4,%4}, p;\n\t}"
                 :: "r"(d), "l"(a), "l"(b), "r"(idesc), "r"(0u), "r"(en) : "memory");
}
__device__ __forceinline__ void mbar_wait(uint32_t mbar, uint32_t parity) {
    uint32_t done;
    asm volatile("{\n\t.reg .pred p;\n\t"
                 "mbarrier.try_wait.parity.acquire.cta.shared::cta.b64 p, [%1], %2;\n\t"
                 "selp.b32 %0, 1, 0, p;\n\t}"
                 : "=r"(done) : "r"(mbar), "r"(parity) : "memory");
    if (!done) {
        asm volatile("{\n\t.reg .pred P1;\n\t"
                     "WAIT_LOOP_%=:\n\t"
                     "mbarrier.try_wait.parity.acquire.cta.shared::cta.b64 P1, [%0], %1, 0x989680;\n\t"
                     "@P1 bra.uni WAIT_DONE_%=;\n\t"
                     "bra.uni WAIT_LOOP_%=;\n\t"
                     "WAIT_DONE_%=:\n\t}"
                     :: "r"(mbar), "r"(parity) : "memory");
    }
}
#define LDTM_X32(r, addr) \
    asm volatile( \
        "tcgen05.ld.sync.aligned.32x32b.x32.b32 " \
        "{%0, %1, %2, %3, %4, %5, %6, %7, " \
        " %8, %9, %10, %11, %12, %13, %14, %15, " \
        " %16, %17, %18, %19, %20, %21, %22, %23, " \
        " %24, %25, %26, %27, %28, %29, %30, %31}, [%32];" \
        : "=r"((r)[0]),  "=r"((r)[1]),  "=r"((r)[2]),  "=r"((r)[3]), \
          "=r"((r)[4]),  "=r"((r)[5]),  "=r"((r)[6]),  "=r"((r)[7]), \
          "=r"((r)[8]),  "=r"((r)[9]),  "=r"((r)[10]), "=r"((r)[11]), \
          "=r"((r)[12]), "=r"((r)[13]), "=r"((r)[14]), "=r"((r)[15]), \
          "=r"((r)[16]), "=r"((r)[17]), "=r"((r)[18]), "=r"((r)[19]), \
          "=r"((r)[20]), "=r"((r)[21]), "=r"((r)[22]), "=r"((r)[23]), \
          "=r"((r)[24]), "=r"((r)[25]), "=r"((r)[26]), "=r"((r)[27]), \
          "=r"((r)[28]), "=r"((r)[29]), "=r"((r)[30]), "=r"((r)[31]) \
        : "r"(addr))
#endif  // HAVE_TCGEN05

// ---------------- pipelined tcgen05 GEMM (unchanged from R10) ----------------
#define SM_TMEM 0
#define SM_MB0  8
#define SM_MB1  16
#define SM_MB2  24
#define SM_AHI  1024
#define SM_ALO  33792
#define SM_B0HI 66560
#define SM_B0LO 99328
#define SM_B1HI 132096
#define SM_B1LO 164864
#define TC_SMEM 197632
#define TMEM_COLS 512

#if HAVE_TCGEN05
__device__ __forceinline__ void tc_copyB(char* smem, uint32_t dsthi, uint32_t dstlo,
                                         int w, int tid)
{
    const uint4* shi = (const uint4*)(g_whi + w * 8192);
    const uint4* slo = (const uint4*)(g_wlo + w * 8192);
    uint4* dhi = (uint4*)(smem + dsthi);
    uint4* dlo = (uint4*)(smem + dstlo);
    for (int i = tid; i < 2048; i += 256) { dhi[i] = shi[i]; dlo[i] = slo[i]; }
}

__device__ __forceinline__ void tc_issue_mma(uint32_t tmem_d, uint64_t ahi, uint64_t alo,
                                             uint64_t bhi, uint64_t blo, uint32_t mbar)
{
    const uint32_t IDESC = (1u << 4) | (1u << 7) | (1u << 10) | (16u << 17) | (8u << 24);
    uint32_t en = 0;
    #pragma unroll
    for (int kc = 0; kc < 8; kc++) {
        uint64_t ko = (uint64_t)((kc & 3) * 2 + (kc >> 2) * 1024);
        mma_f16_ss(tmem_d, ahi + ko, bhi + ko, IDESC, en); en = 1;
    }
    #pragma unroll
    for (int kc = 0; kc < 8; kc++) {
        uint64_t ko = (uint64_t)((kc & 3) * 2 + (kc >> 2) * 1024);
        mma_f16_ss(tmem_d, ahi + ko, blo + ko, IDESC, 1);
    }
    #pragma unroll
    for (int kc = 0; kc < 8; kc++) {
        uint64_t ko = (uint64_t)((kc & 3) * 2 + (kc >> 2) * 1024);
        mma_f16_ss(tmem_d, alo + ko, bhi + ko, IDESC, 1);
    }
    asm volatile("tcgen05.commit.cta_group::1.mbarrier::arrive::one.shared::cluster.b64 [%0];"
                 :: "r"(mbar) : "memory");
}

__device__ __forceinline__ void tc_epilogue(uint32_t tmem_d, int M, int row0,
                                            int wid, int lane, int mode,
                                            const float* bias, float* C)
{
    if (wid >= 4) return;
    int gr = row0 + wid * 32 + lane;
    #pragma unroll 1
    for (int cb = 0; cb < 4; cb++) {
        uint32_t d[32];
        LDTM_X32(d, tmem_d + cb * 32);
        asm volatile("tcgen05.wait::ld.sync.aligned;" ::: "memory");
        if (gr < M) {
            float* dst = C + (size_t)gr * 128 + cb * 32;
            if (mode == 1) {
                const float4* mvp = (const float4*)(g_mv + (size_t)gr * 128 + cb * 32);
                const float4* t0p = (const float4*)(g_t0 + (size_t)(gr / 3) * 128 + cb * 32);
                #pragma unroll
                for (int q = 0; q < 8; q++) {
                    float4 mv = mvp[q], t0 = t0p[q];
                    float4 o;
                    o.x = mv.x + t0.x * __uint_as_float(d[q * 4 + 0]);
                    o.y = mv.y + t0.y * __uint_as_float(d[q * 4 + 1]);
                    o.z = mv.z + t0.z * __uint_as_float(d[q * 4 + 2]);
                    o.w = mv.w + t0.w * __uint_as_float(d[q * 4 + 3]);
                    ((float4*)dst)[q] = o;
                }
            } else {
                #pragma unroll
                for (int q = 0; q < 8; q++) {
                    float4 o;
                    o.x = __uint_as_float(d[q * 4 + 0]);
                    o.y = __uint_as_float(d[q * 4 + 1]);
                    o.z = __uint_as_float(d[q * 4 + 2]);
                    o.w = __uint_as_float(d[q * 4 + 3]);
                    if (bias) {
                        const float* bb = bias + cb * 32 + q * 4;
                        o.x += bb[0]; o.y += bb[1]; o.z += bb[2]; o.w += bb[3];
                    }
                    ((float4*)dst)[q] = o;
                }
            }
        }
    }
}
#endif  // HAVE_TCGEN05

__global__ __launch_bounds__(256, 1) __cluster_dims__(1, 1, 1)
void tc_gemm(const float* __restrict__ A, int M,
             int w0, int m0, const float* __restrict__ W0f, const float* __restrict__ b0, float* __restrict__ C0,
             int w1, int m1, const float* __restrict__ W1f, const float* __restrict__ b1, float* __restrict__ C1,
             int w2, int m2, const float* __restrict__ W2f, const float* __restrict__ b2, float* __restrict__ C2)
{
#if HAVE_TCGEN05
    extern __shared__ char smem[];
    uint32_t sb = smem_u32(smem);
    int tid = threadIdx.x, wid = tid >> 5, lane = tid & 31;
    int row0 = blockIdx.x * 128;

    if (wid == 0)
        asm volatile("tcgen05.alloc.cta_group::1.sync.aligned.shared::cta.b32 [%0], %1;"
                     :: "r"(sb + SM_TMEM), "r"((uint32_t)TMEM_COLS) : "memory");
    if (tid == 0) {
        asm volatile("mbarrier.init.shared.b64 [%0], 1;" :: "r"(sb + SM_MB0) : "memory");
        asm volatile("mbarrier.init.shared.b64 [%0], 1;" :: "r"(sb + SM_MB1) : "memory");
        asm volatile("mbarrier.init.shared.b64 [%0], 1;" :: "r"(sb + SM_MB2) : "memory");
    }
    __syncthreads();
    uint32_t tmem;
    asm volatile("ld.shared.b32 %0, [%1];" : "=r"(tmem) : "r"(sb + SM_TMEM));

    for (int p = tid; p < 8192; p += 256) {
        int r = p >> 6, k2 = (p & 63) * 2;
        float2 x = make_float2(0.f, 0.f);
        if (row0 + r < M) x = *(const float2*)(A + (size_t)(row0 + r) * 128 + k2);
        __nv_bfloat16 h0 = __float2bfloat16(x.x), h1 = __float2bfloat16(x.y);
        float r0f = x.x - __bfloat162float(h0), r1f = x.y - __bfloat162float(h1);
        __nv_bfloat16 l0 = __float2bfloat16(r0f), l1 = __float2bfloat16(r1f);
        uint32_t hiw = (uint32_t)__bfloat16_as_ushort(h0)
                     | ((uint32_t)__bfloat16_as_ushort(h1) << 16);
        uint32_t low = (uint32_t)__bfloat16_as_ushort(l0)
                     | ((uint32_t)__bfloat16_as_ushort(l1) << 16);
        uint32_t off = blk_off(r, k2);
        *(uint32_t*)(smem + SM_AHI + off) = hiw;
        *(uint32_t*)(smem + SM_ALO + off) = low;
    }

    const uint64_t DESCB = (2ull << 61) | (1ull << 46) | (64ull << 32) | (1ull << 16);
    uint64_t ahi  = DESCB | ((uint64_t)((sb + SM_AHI)  >> 4) & 0x3FFF);
    uint64_t alo  = DESCB | ((uint64_t)((sb + SM_ALO)  >> 4) & 0x3FFF);
    uint64_t b0hi = DESCB | ((uint64_t)((sb + SM_B0HI) >> 4) & 0x3FFF);
    uint64_t b0lo = DESCB | ((uint64_t)((sb + SM_B0LO) >> 4) & 0x3FFF);
    uint64_t b1hi = DESCB | ((uint64_t)((sb + SM_B1HI) >> 4) & 0x3FFF);
    uint64_t b1lo = DESCB | ((uint64_t)((sb + SM_B1LO) >> 4) & 0x3FFF);

    tc_copyB(smem, SM_B0HI, SM_B0LO, w0, tid);
    asm volatile("fence.proxy.async.shared::cta;" ::: "memory");
    __syncthreads();
    if (wid == 0 && elect1())
        tc_issue_mma(tmem, ahi, alo, b0hi, b0lo, sb + SM_MB0);

    if (w1 >= 0) {
        tc_copyB(smem, SM_B1HI, SM_B1LO, w1, tid);
        asm volatile("fence.proxy.async.shared::cta;" ::: "memory");
        __syncthreads();
        if (wid == 0 && elect1())
            tc_issue_mma(tmem + 128, ahi, alo, b1hi, b1lo, sb + SM_MB1);
    }

    mbar_wait(sb + SM_MB0, 0);
    asm volatile("tcgen05.fence::after_thread_sync;" ::: "memory");
    if (w2 >= 0) {
        tc_copyB(smem, SM_B0HI, SM_B0LO, w2, tid);
        asm volatile("fence.proxy.async.shared::cta;" ::: "memory");
        __syncthreads();
        if (wid == 0 && elect1())
            tc_issue_mma(tmem + 256, ahi, alo, b0hi, b0lo, sb + SM_MB2);
    }

    tc_epilogue(tmem, M, row0, wid, lane, m0, b0, C0);
    if (w1 >= 0) {
        mbar_wait(sb + SM_MB1, 0);
        asm volatile("tcgen05.fence::after_thread_sync;" ::: "memory");
        tc_epilogue(tmem + 128, M, row0, wid, lane, m1, b1, C1);
    }
    if (w2 >= 0) {
        mbar_wait(sb + SM_MB2, 0);
        asm volatile("tcgen05.fence::after_thread_sync;" ::: "memory");
        tc_epilogue(tmem + 256, M, row0, wid, lane, m2, b2, C2);
    }
    asm volatile("tcgen05.fence::before_thread_sync;" ::: "memory");
    __syncthreads();

    if (tid == 0) {
        asm volatile("mbarrier.inval.shared.b64 [%0];" :: "r"(sb + SM_MB0) : "memory");
        asm volatile("mbarrier.inval.shared.b64 [%0];" :: "r"(sb + SM_MB1) : "memory");
        asm volatile("mbarrier.inval.shared.b64 [%0];" :: "r"(sb + SM_MB2) : "memory");
    }
    __syncthreads();
    if (wid == 0)
        asm volatile("tcgen05.dealloc.cta_group::1.sync.aligned.b32 %0, %1;"
                     :: "r"(tmem), "r"((uint32_t)TMEM_COLS));

#else  // SIMT fp32 fallback
    extern __shared__ float smf[];
    float* sA = smf;
    float* sW = smf + 16384;
    int tid = threadIdx.x;
    int row0 = blockIdx.x * 128;

    for (int i = tid; i < 4096; i += 256) {
        int r  = i >> 5;
        int gr = row0 + r;
        float4 v = make_float4(0.f, 0.f, 0.f, 0.f);
        if (gr < M) v = ((const float4*)A)[(size_t)gr * 32 + (i & 31)];
        ((float4*)sA)[i] = v;
    }

    const float* Wf[3] = {W0f, W1f, W2f};
    const float* bpf[3] = {b0, b1, b2};
    float* cpf[3] = {C0, C1, C2};
    int widxf[3] = {w0, w1, w2};
    int modef[3] = {m0, m1, m2};

    #pragma unroll 1
    for (int j = 0; j < 3; j++) {
        if (widxf[j] < 0) break;
        __syncthreads();
        for (int i = tid; i < 4096; i += 256)
            ((float4*)sW)[i] = ((const float4*)Wf[j])[i];
        __syncthreads();

        int rb = tid >> 4, cb = tid & 15;
        float acc[8][8];
        #pragma unroll
        for (int i = 0; i < 8; i++)
            #pragma unroll
            for (int q = 0; q < 8; q++) acc[i][q] = 0.f;

        #pragma unroll 4
        for (int k = 0; k < 128; k++) {
            float4 wv0 = *(const float4*)&sW[k * 128 + cb * 8];
            float4 wv1 = *(const float4*)&sW[k * 128 + cb * 8 + 4];
            float w[8] = {wv0.x, wv0.y, wv0.z, wv0.w, wv1.x, wv1.y, wv1.z, wv1.w};
            float a[8];
            #pragma unroll
            for (int i = 0; i < 8; i++) a[i] = sA[(rb * 8 + i) * 128 + k];
            #pragma unroll
            for (int i = 0; i < 8; i++)
                #pragma unroll
                for (int q = 0; q < 8; q++) acc[i][q] += a[i] * w[q];
        }

        #pragma unroll
        for (int i = 0; i < 8; i++) {
            int gr = row0 + rb * 8 + i;
            if (gr < M) {
                float* dst = cpf[j] + (size_t)gr * 128 + cb * 8;
                for (int q = 0; q < 8; q++) {
                    float o = acc[i][q];
                    if (modef[j] == 1)
                        o = g_mv[(size_t)gr * 128 + cb * 8 + q]
                          + g_t0[(size_t)(gr / 3) * 128 + cb * 8 + q] * o;
                    else if (bpf[j]) o += bpf[j][cb * 8 + q];
                    dst[q] = o;
                }
            }
        }
    }
#endif
}

// ---------------- P precompute ----------------
__global__ void pprep_kernel(const float* __restrict__ Wp1,
                             const float* __restrict__ Ws1)
{
    int idx = blockIdx.x * blockDim.x + threadIdx.x;
    if (idx >= GG * 512) return;
    int g  = idx >> 9;
    int hc = idx & 511;
    int h  = hc >> 6, c = hc & 63;
    const float* vp = g_val + (size_t)g * 128 + h * 16;
    float sp = 0.f, ss = 0.f;
    #pragma unroll
    for (int i = 0; i < 16; i++) {
        float v = vp[i];
        int wrow = (h * 16 + i) * 64 + c;
        sp += v * Wp1[wrow];
        ss += v * Ws1[wrow];
    }
    g_Pp[idx] = sp;
    g_Ps[idx] = ss;
}

// ---------------- fused edge kernel: 128-edge tiles, tcgen05 layer-2 ----------------
// SMEM byte offsets
#define XO_W2PH 0         // 16KB  Wp2 hi
#define XO_W2PL 16384     // 16KB  Wp2 lo
#define XO_W2SH 32768     // 16KB  Ws2 hi
#define XO_W2SL 49152     // 16KB  Ws2 lo
#define XO_AHPH 65536     // 16KB  hidden_p hi   (fallback: hp fp32 32KB at 65536)
#define XO_AHPL 81920     // 16KB  hidden_p lo
#define XO_AHSH 98304     // 16KB  hidden_s hi   (fallback: hs fp32 32KB at 98304)
#define XO_AHSL 114688    // 16KB  hidden_s lo
#define XO_ATT  131072    // 4KB   attn [128][8]
#define XO_U    135168    // 1.5KB u [128][3]
#define XO_N    136704    // 512B
#define XO_G    137216    // 512B
#define XO_BP1  137728    // 256B
#define XO_BS1  137984
#define XO_BP2  138240    // 512B
#define XO_BS2  138752
#define XO_TM   139264    // 8B tmem ptr
#define XO_MBAR 139272    // 8B
#define EDGE_SMEM_BYTES 139328
#define ETILE 128
#define NTILES (EE / ETILE)   // 3125

__global__ __launch_bounds__(512, 1) __cluster_dims__(1, 1, 1)
void edge_kernel(
    const int*   __restrict__ node_idx,
    const int*   __restrict__ group_idx,
    const float* __restrict__ edge_attr,
    const float* __restrict__ edge_vec,
    const float* __restrict__ bp1, const float* __restrict__ bs1,
    const float* __restrict__ Wp2, const float* __restrict__ bp2,
    const float* __restrict__ Ws2, const float* __restrict__ bs2,
    const float* __restrict__ gvec)
{
    extern __shared__ char smx[];
    uint32_t sb = smem_u32(smx);
    int tid = threadIdx.x, wid = tid >> 5, lane = tid & 31;

    float* s_attn = (float*)(smx + XO_ATT);
    float* s_u    = (float*)(smx + XO_U);
    int*   s_n    = (int*)(smx + XO_N);
    int*   s_g    = (int*)(smx + XO_G);
    float* s_bp1  = (float*)(smx + XO_BP1);
    float* s_bs1  = (float*)(smx + XO_BS1);
    float* s_bp2  = (float*)(smx + XO_BP2);
    float* s_bs2  = (float*)(smx + XO_BS2);

    if (tid < 64)  { s_bp1[tid] = bp1[tid]; s_bs1[tid] = bs1[tid]; }
    if (tid < 128) { s_bp2[tid] = bp2[tid]; s_bs2[tid] = bs2[tid]; }

#if HAVE_TCGEN05
    // W2 tiles (bf16 hi/lo) into SMEM once per block
    for (int i = tid; i < 1024; i += 512) {
        ((uint4*)(smx + XO_W2PH))[i] = ((const uint4*)g_w2hi)[i];
        ((uint4*)(smx + XO_W2PL))[i] = ((const uint4*)g_w2lo)[i];
        ((uint4*)(smx + XO_W2SH))[i] = ((const uint4*)g_w2hi)[1024 + i];
        ((uint4*)(smx + XO_W2SL))[i] = ((const uint4*)g_w2lo)[1024 + i];
    }
    if (wid == 0)
        asm volatile("tcgen05.alloc.cta_group::1.sync.aligned.shared::cta.b32 [%0], %1;"
                     :: "r"(sb + XO_TM), "r"((uint32_t)TMEM_COLS) : "memory");
    if (tid == 0)
        asm volatile("mbarrier.init.shared.b64 [%0], 1;" :: "r"(sb + XO_MBAR) : "memory");
    __syncthreads();
    uint32_t tmem;
    asm volatile("ld.shared.b32 %0, [%1];" : "=r"(tmem) : "r"(sb + XO_TM));

    const uint64_t DESCB = (2ull << 61) | (1ull << 46) | (64ull << 32) | (1ull << 16);
    uint64_t aph = DESCB | ((uint64_t)((sb + XO_AHPH) >> 4) & 0x3FFF);
    uint64_t apl = DESCB | ((uint64_t)((sb + XO_AHPL) >> 4) & 0x3FFF);
    uint64_t ash = DESCB | ((uint64_t)((sb + XO_AHSH) >> 4) & 0x3FFF);
    uint64_t asl = DESCB | ((uint64_t)((sb + XO_AHSL) >> 4) & 0x3FFF);
    uint64_t wph = DESCB | ((uint64_t)((sb + XO_W2PH) >> 4) & 0x3FFF);
    uint64_t wpl = DESCB | ((uint64_t)((sb + XO_W2PL) >> 4) & 0x3FFF);
    uint64_t wsh = DESCB | ((uint64_t)((sb + XO_W2SH) >> 4) & 0x3FFF);
    uint64_t wsl = DESCB | ((uint64_t)((sb + XO_W2SL) >> 4) & 0x3FFF);
    const uint32_t IDESC = (1u << 4) | (1u << 7) | (1u << 10) | (16u << 17) | (8u << 24);
    uint32_t ph = 0;
#else
    __syncthreads();
#endif

    for (int t = blockIdx.x; t < NTILES; t += gridDim.x) {
        int e0 = t * ETILE;

        // phase 0: edge metadata (group-sorted order)
        if (tid < 128) {
            int e = g_perm[e0 + tid];
            s_n[tid] = node_idx[e];
            s_g[tid] = group_idx[e];
            // stash e in s_attn temporarily? no — store u now, reload attr by e below
            s_u[tid * 3 + 0] = -edge_vec[e * 3 + 0];
            s_u[tid * 3 + 1] = -edge_vec[e * 3 + 1];
            s_u[tid * 3 + 2] = -edge_vec[e * 3 + 2];
            // keep e in smem via reuse of attn area (before attn written)
            ((int*)(smx + XO_ATT))[tid] = e;
        }
        __syncthreads();

        // phase 1: attention (128 edges x 8 heads) — must read s_e before attn overwrite
        {
            int eloc[2];
            eloc[0] = ((int*)(smx + XO_ATT))[(tid) >> 3 >= 128 ? 0 : ((tid) >> 3)];
            eloc[1] = ((int*)(smx + XO_ATT))[((tid + 512) >> 3)];
            float dots[2];
            #pragma unroll
            for (int r = 0; r < 2; r++) {
                int p = tid + r * 512;
                int le = p >> 3, h = p & 7;
                const float4* qp = (const float4*)(g_q + (size_t)s_n[le] * 128 + h * 16);
                const float4* kp = (const float4*)(g_k + (size_t)s_g[le] * 128 + h * 16);
                const float4* ep = (const float4*)(edge_attr + (size_t)eloc[r] * 128 + h * 16);
                float dot = 0.f;
                #pragma unroll
                for (int c = 0; c < 4; c++) {
                    float4 qv = qp[c], kv = kp[c], ev = ep[c];
                    dot += qv.x * kv.x * ev.x + qv.y * kv.y * ev.y
                         + qv.z * kv.z * ev.z + qv.w * kv.w * ev.w;
                }
                dots[r] = silu_f(dot * 0.25f);
            }
            __syncthreads();   // all e reads done before attn overwrite
            s_attn[tid] = dots[0];
            s_attn[tid + 512] = dots[1];
        }
        __syncthreads();

        // phase 2: m_s scatter (128 edges x 32 float4)
        for (int i4 = tid; i4 < 4096; i4 += 512) {
            int le = i4 >> 5, j4 = i4 & 31;
            float4 v = ((const float4*)(g_val + (size_t)s_g[le] * 128))[j4];
            float  a = s_attn[le * 8 + (j4 >> 2)];
            float4 m = make_float4(v.x * a, v.y * a, v.z * a, v.w * a);
            atomicAdd((float4*)(g_ms + (size_t)s_n[le] * 128 + j4 * 4), m);
        }

        // phase 3: hidden = silu(sum_h attn*P + b1); stage for layer-2
        {
            int le = tid >> 2, cq = tid & 3, c0 = cq * 16;
            int g = s_g[le];
            float at[8];
            #pragma unroll
            for (int h = 0; h < 8; h++) at[h] = s_attn[le * 8 + h];
            float hp[16], hs[16];
            #pragma unroll
            for (int j = 0; j < 16; j++) { hp[j] = 0.f; hs[j] = 0.f; }
            const float4* Pp4 = (const float4*)(g_Pp + (size_t)g * 512);
            const float4* Ps4 = (const float4*)(g_Ps + (size_t)g * 512);
            #pragma unroll
            for (int h = 0; h < 8; h++) {
                int base = h * 16 + cq * 4;
                float ah = at[h];
                #pragma unroll
                for (int q = 0; q < 4; q++) {
                    float4 p = Pp4[base + q];
                    float4 s = Ps4[base + q];
                    hp[q*4+0] += ah * p.x; hp[q*4+1] += ah * p.y;
                    hp[q*4+2] += ah * p.z; hp[q*4+3] += ah * p.w;
                    hs[q*4+0] += ah * s.x; hs[q*4+1] += ah * s.y;
                    hs[q*4+2] += ah * s.z; hs[q*4+3] += ah * s.w;
                }
            }
#if HAVE_TCGEN05
            #pragma unroll
            for (int jp = 0; jp < 8; jp++) {
                float p0 = silu_f(hp[jp*2]   + s_bp1[c0 + jp*2]);
                float p1 = silu_f(hp[jp*2+1] + s_bp1[c0 + jp*2+1]);
                float q0 = silu_f(hs[jp*2]   + s_bs1[c0 + jp*2]);
                float q1 = silu_f(hs[jp*2+1] + s_bs1[c0 + jp*2+1]);
                __nv_bfloat16 ph0 = __float2bfloat16(p0), ph1 = __float2bfloat16(p1);
                __nv_bfloat16 qh0 = __float2bfloat16(q0), qh1 = __float2bfloat16(q1);
                float pr0 = p0 - __bfloat162float(ph0), pr1 = p1 - __bfloat162float(ph1);
                float qr0 = q0 - __bfloat162float(qh0), qr1 = q1 - __bfloat162float(qh1);
                __nv_bfloat16 pl0 = __float2bfloat16(pr0), pl1 = __float2bfloat16(pr1);
                __nv_bfloat16 ql0 = __float2bfloat16(qr0), ql1 = __float2bfloat16(qr1);
                uint32_t off = blk64_off(le, c0 + jp * 2);
                *(uint32_t*)(smx + XO_AHPH + off) =
                    (uint32_t)__bfloat16_as_ushort(ph0) | ((uint32_t)__bfloat16_as_ushort(ph1) << 16);
                *(uint32_t*)(smx + XO_AHPL + off) =
                    (uint32_t)__bfloat16_as_ushort(pl0) | ((uint32_t)__bfloat16_as_ushort(pl1) << 16);
                *(uint32_t*)(smx + XO_AHSH + off) =
                    (uint32_t)__bfloat16_as_ushort(qh0) | ((uint32_t)__bfloat16_as_ushort(qh1) << 16);
                *(uint32_t*)(smx + XO_AHSL + off) =
                    (uint32_t)__bfloat16_as_ushort(ql0) | ((uint32_t)__bfloat16_as_ushort(ql1) << 16);
            }
#else
            float* fhp = (float*)(smx + XO_AHPH);   // [128][64] fp32
            float* fhs = (float*)(smx + XO_AHSH);
            #pragma unroll
            for (int j = 0; j < 16; j++) {
                fhp[le * 64 + c0 + j] = silu_f(hp[j] + s_bp1[c0 + j]);
                fhs[le * 64 + c0 + j] = silu_f(hs[j] + s_bs1[c0 + j]);
            }
#endif
        }

#if HAVE_TCGEN05
        asm volatile("fence.proxy.async.shared::cta;" ::: "memory");
        __syncthreads();

        // layer-2 on tensor cores: sp = hp@Wp2 (D cols 0-127), sv = hs@Ws2 (cols 128-255)
        if (wid == 0 && elect1()) {
            uint32_t en = 0;
            #pragma unroll
            for (int kc = 0; kc < 4; kc++) {
                uint64_t ko = (uint64_t)(kc * 2);
                mma_f16_ss(tmem, aph + ko, wph + ko, IDESC, en); en = 1;
            }
            #pragma unroll
            for (int kc = 0; kc < 4; kc++) {
                uint64_t ko = (uint64_t)(kc * 2);
                mma_f16_ss(tmem, aph + ko, wpl + ko, IDESC, 1);
                mma_f16_ss(tmem, apl + ko, wph + ko, IDESC, 1);
            }
            en = 0;
            #pragma unroll
            for (int kc = 0; kc < 4; kc++) {
                uint64_t ko = (uint64_t)(kc * 2);
                mma_f16_ss(tmem + 128, ash + ko, wsh + ko, IDESC, en); en = 1;
            }
            #pragma unroll
            for (int kc = 0; kc < 4; kc++) {
                uint64_t ko = (uint64_t)(kc * 2);
                mma_f16_ss(tmem + 128, ash + ko, wsl + ko, IDESC, 1);
                mma_f16_ss(tmem + 128, asl + ko, wsh + ko, IDESC, 1);
            }
            asm volatile("tcgen05.commit.cta_group::1.mbarrier::arrive::one.shared::cluster.b64 [%0];"
                         :: "r"(sb + XO_MBAR) : "memory");
        }
        mbar_wait(sb + XO_MBAR, ph); ph ^= 1;
        asm volatile("tcgen05.fence::after_thread_sync;" ::: "memory");

        // epilogue: warps 0-3; lane = edge within subpartition; m_v scatter
        if (wid < 4) {
            int le = wid * 32 + lane;
            int n = s_n[le], g = s_g[le];
            float u0 = s_u[le * 3], u1 = s_u[le * 3 + 1], u2 = s_u[le * 3 + 2];
            #pragma unroll 1
            for (int cb = 0; cb < 4; cb++) {
                uint32_t dsp[32], dsv[32];
                LDTM_X32(dsp, tmem + cb * 32);
                LDTM_X32(dsv, tmem + 128 + cb * 32);
                asm volatile("tcgen05.wait::ld.sync.aligned;" ::: "memory");
                float* spv = (float*)dsp;
                float* svv = (float*)dsv;
                #pragma unroll
                for (int j = 0; j < 32; j++) {
                    spv[j] = __uint_as_float(dsp[j]) + s_bp2[cb * 32 + j];
                    svv[j] = __uint_as_float(dsv[j]) + s_bs2[cb * 32 + j];
                }
                float uu[3] = {u0, u1, u2};
                #pragma unroll
                for (int d = 0; d < 3; d++) {
                    const float4* gv4 = (const float4*)(gvec + (size_t)g * 384 + d * 128 + cb * 32);
                    float* dst = g_mv + (size_t)n * 384 + d * 128 + cb * 32;
                    float ud = uu[d];
                    #pragma unroll
                    for (int q = 0; q < 8; q++) {
                        float4 gv = gv4[q];
                        float4 o;
                        o.x = spv[q*4+0] * ud + svv[q*4+0] * gv.x;
                        o.y = spv[q*4+1] * ud + svv[q*4+1] * gv.y;
                        o.z = spv[q*4+2] * ud + svv[q*4+2] * gv.z;
                        o.w = spv[q*4+3] * ud + svv[q*4+3] * gv.w;
                        atomicAdd((float4*)(dst + q * 4), o);
                    }
                }
            }
            asm volatile("tcgen05.fence::before_thread_sync;" ::: "memory");
        }
        __syncthreads();
#else
        __syncthreads();
        // SIMT layer-2 fallback
        {
            const float* fhp = (const float*)(smx + XO_AHPH);
            const float* fhs = (const float*)(smx + XO_AHSH);
            int rg = tid >> 4, cg = tid & 15;   // 32 groups x 4 edges; cols cg*8
            float sp[4][8], sv[4][8];
            #pragma unroll
            for (int i = 0; i < 4; i++)
                #pragma unroll
                for (int j = 0; j < 8; j++) { sp[i][j] = 0.f; sv[i][j] = 0.f; }
            for (int k = 0; k < 64; k++) {
                float wp[8], ws[8];
                #pragma unroll
                for (int j = 0; j < 8; j++) {
                    wp[j] = Wp2[k * 128 + cg * 8 + j];
                    ws[j] = Ws2[k * 128 + cg * 8 + j];
                }
                #pragma unroll
                for (int i = 0; i < 4; i++) {
                    float hpv = fhp[(rg * 4 + i) * 64 + k];
                    float hsv = fhs[(rg * 4 + i) * 64 + k];
                    #pragma unroll
                    for (int j = 0; j < 8; j++) {
                        sp[i][j] += hpv * wp[j];
                        sv[i][j] += hsv * ws[j];
                    }
                }
            }
            #pragma unroll
            for (int i = 0; i < 4; i++) {
                int le = rg * 4 + i;
                int n = s_n[le], g = s_g[le];
                #pragma unroll
                for (int d = 0; d < 3; d++) {
                    float ud = s_u[le * 3 + d];
                    const float* gv = gvec + (size_t)g * 384 + d * 128 + cg * 8;
                    float* dst = g_mv + (size_t)n * 384 + d * 128 + cg * 8;
                    #pragma unroll
                    for (int j = 0; j < 8; j += 4) {
                        float4 o;
                        o.x = (sp[i][j+0] + s_bp2[cg*8+j+0]) * ud + (sv[i][j+0] + s_bs2[cg*8+j+0]) * gv[j+0];
                        o.y = (sp[i][j+1] + s_bp2[cg*8+j+1]) * ud + (sv[i][j+1] + s_bs2[cg*8+j+1]) * gv[j+1];
                        o.z = (sp[i][j+2] + s_bp2[cg*8+j+2]) * ud + (sv[i][j+2] + s_bs2[cg*8+j+2]) * gv[j+2];
                        o.w = (sp[i][j+3] + s_bp2[cg*8+j+3]) * ud + (sv[i][j+3] + s_bs2[cg*8+j+3]) * gv[j+3];
                        atomicAdd((float4*)(dst + j), o);
                    }
                }
            }
        }
        __syncthreads();
#endif
    }

#if HAVE_TCGEN05
    if (tid == 0)
        asm volatile("mbarrier.inval.shared.b64 [%0];" :: "r"(sb + XO_MBAR) : "memory");
    __syncthreads();
    if (wid == 0)
        asm volatile("tcgen05.dealloc.cta_group::1.sync.aligned.b32 %0, %1;"
                     :: "r"(tmem), "r"((uint32_t)TMEM_COLS));
#endif
}

// ---------------- finalize: dx only ----------------
__global__ void finalize_kernel(float* __restrict__ out) {
    int idx = blockIdx.x * blockDim.x + threadIdx.x;
    if (idx >= NN * 32) return;
    int n = idx >> 5, j4 = idx & 31;
    size_t off = (size_t)n * 32 + j4;
    float4 t4 = ((const float4*)g_t4)[off];
    float4 t5 = ((const float4*)g_t5)[off];
    float4 s3 = make_float4(0.f, 0.f, 0.f, 0.f);
    #pragma unroll
    for (int d = 0; d < 3; d++) {
        size_t roff = ((size_t)n * 3 + d) * 32 + j4;
        float4 v1 = ((const float4*)g_v1)[roff];
        float4 v2 = ((const float4*)g_v2)[roff];
        s3.x += v1.x * v2.x; s3.y += v1.y * v2.y;
        s3.z += v1.z * v2.z; s3.w += v1.w * v2.w;
    }
    float4 dx = make_float4(s3.x * t4.x + t5.x, s3.y * t4.y + t5.y,
                            s3.z * t4.z + t5.z, s3.w * t4.w + t5.w);
    ((float4*)out)[off] = dx;
}

// ---------------- launch ----------------
extern "C" void kernel_launch(void* const* d_in, const int* in_sizes, int n_in,
                              void* d_out, int out_size)
{
    (void)in_sizes; (void)n_in; (void)out_size;
    const int*   node_idx   = (const int*)  d_in[0];
    const int*   group_idx  = (const int*)  d_in[1];
    const float* node_emb   = (const float*)d_in[2];
    const float* node_vec   = (const float*)d_in[3];
    const float* group_emb  = (const float*)d_in[4];
    const float* group_vec  = (const float*)d_in[5];
    const float* edge_attr  = (const float*)d_in[6];
    const float* edge_vec   = (const float*)d_in[8];
    const float* Wq  = (const float*)d_in[9];
    const float* bq  = (const float*)d_in[10];
    const float* Wk  = (const float*)d_in[11];
    const float* bk  = (const float*)d_in[12];
    const float* Wv  = (const float*)d_in[13];
    const float* bv  = (const float*)d_in[14];
    const float* Wp1 = (const float*)d_in[15];
    const float* bp1 = (const float*)d_in[16];
    const float* Wp2 = (const float*)d_in[17];
    const float* bp2 = (const float*)d_in[18];
    const float* Ws1 = (const float*)d_in[19];
    const float* bs1 = (const float*)d_in[20];
    const float* Ws2 = (const float*)d_in[21];
    const float* bs2 = (const float*)d_in[22];
    const float* L0  = (const float*)d_in[23];
    const float* L1  = (const float*)d_in[24];
    const float* L2  = (const float*)d_in[25];
    const float* L3  = (const float*)d_in[26];
    const float* L4  = (const float*)d_in[27];
    const float* L5  = (const float*)d_in[28];
    float* out = (float*)d_out;

    cudaFuncSetAttribute(tc_gemm, cudaFuncAttributeMaxDynamicSharedMemorySize, TC_SMEM);
    cudaFuncSetAttribute(edge_kernel, cudaFuncAttributeMaxDynamicSharedMemorySize,
                         EDGE_SMEM_BYTES);

    float *p_q, *p_k, *p_val, *p_ms, *p_mv, *p_t0, *p_t4, *p_t5, *p_v1, *p_v2;
    int *p_cnt;
    cudaGetSymbolAddress((void**)&p_q,  g_q);
    cudaGetSymbolAddress((void**)&p_k,  g_k);
    cudaGetSymbolAddress((void**)&p_val,g_val);
    cudaGetSymbolAddress((void**)&p_ms, g_ms);
    cudaGetSymbolAddress((void**)&p_mv, g_mv);
    cudaGetSymbolAddress((void**)&p_t0, g_t0);
    cudaGetSymbolAddress((void**)&p_t4, g_t4);
    cudaGetSymbolAddress((void**)&p_t5, g_t5);
    cudaGetSymbolAddress((void**)&p_v1, g_v1);
    cudaGetSymbolAddress((void**)&p_v2, g_v2);
    cudaGetSymbolAddress((void**)&p_cnt, g_cnt);

    float* out_dv = out + (size_t)NN * 128;

    // 1) zero accumulators + sort scratch
    cudaMemsetAsync(p_ms, 0, (size_t)NN * 128 * sizeof(float));
    cudaMemsetAsync(p_mv, 0, (size_t)NN * 384 * sizeof(float));
    cudaMemsetAsync(p_cnt, 0, (size_t)GG * sizeof(int));

    // 2) group-sort the edges
    hist_kernel<<<(EE + 255) / 256, 256>>>(group_idx);
    scan_kernel<<<1, 1024>>>();
    scatter_kernel<<<(EE + 255) / 256, 256>>>(group_idx);

    // 3) weight conversions
    wconv_kernel<<<(9 * 8192 + 255) / 256, 256>>>(Wq, Wk, Wv, L0, L1, L2, L3, L4, L5);
    wconv2_kernel<<<(2 * 4096 + 255) / 256, 256>>>(Wp2, Ws2);

    // 4) projections on tensor cores
    tc_gemm<<<(NN + 127) / 128, 256, TC_SMEM>>>(node_emb, NN,
        0, 0, Wq, bq, p_q,
        -1, 0, nullptr, nullptr, nullptr,
        -1, 0, nullptr, nullptr, nullptr);
    tc_gemm<<<(GG + 127) / 128, 256, TC_SMEM>>>(group_emb, GG,
        1, 0, Wk, bk, p_k,
        2, 0, Wv, bv, p_val,
        -1, 0, nullptr, nullptr, nullptr);

    // 5) per-group layer-1 factorization tables
    pprep_kernel<<<(GG * 512 + 255) / 256, 256>>>(Wp1, Ws1);

    // 6) fused edge pipeline (group-sorted, tcgen05 layer-2)
    edge_kernel<<<148, 512, EDGE_SMEM_BYTES>>>(node_idx, group_idx, edge_attr, edge_vec,
                                               bp1, bs1, Wp2, bp2, Ws2, bs2, group_vec);

    // 7) node-side GEMMs: ms -> t0/t4/t5 ; node_vec -> dv (fused) / v1 / v2
    tc_gemm<<<(NN + 127) / 128, 256, TC_SMEM>>>(p_ms, NN,
        3, 0, L0, nullptr, p_t0,
        7, 0, L4, nullptr, p_t4,
        8, 0, L5, nullptr, p_t5);
    tc_gemm<<<(3 * NN + 127) / 128, 256, TC_SMEM>>>(node_vec, 3 * NN,
        4, 1, L1, nullptr, out_dv,
        5, 0, L2, nullptr, p_v1,
        6, 0, L3, nullptr, p_v2);

    // 8) finalize dx
    finalize_kernel<<<(NN * 32 + 255) / 256, 256>>>(out);
}

// round 12
// speedup vs baseline: 1.1442x; 1.0497x over previous
#include <cuda_runtime.h>
#include <cuda_bf16.h>
#include <math.h>
#include <stdint.h>

#define NN 100000
#define GG 6000
#define EE 400000

// ---------------- scratch ----------------
__device__ float g_q  [NN * 128];
__device__ float g_k  [GG * 128];
__device__ float g_val[GG * 128];
__device__ float g_ms [NN * 128];
__device__ float g_mv [NN * 384];
__device__ float g_t0 [NN * 128];
__device__ float g_t4 [NN * 128];
__device__ float g_t5 [NN * 128];
__device__ float g_v1 [NN * 384];
__device__ float g_v2 [NN * 384];
__device__ float g_Pp [GG * 512];
__device__ float g_Ps [GG * 512];
__device__ uint32_t g_whi[9 * 8192];
__device__ uint32_t g_wlo[9 * 8192];
__device__ uint32_t g_w2hi[2 * 4096];
__device__ uint32_t g_w2lo[2 * 4096];
__device__ int g_cnt [GG];
__device__ int g_cur [GG];
__device__ int g_perm[EE];

__device__ __forceinline__ float silu_f(float x) {
    return x / (1.0f + __expf(-x));
}

__device__ __forceinline__ uint32_t blk_off(int row, int col) {
    uint32_t off = (uint32_t)((row >> 3) + (col >> 6) * 16) * 1024u
                 + (uint32_t)(row & 7) * 128u + (uint32_t)(col & 63) * 2u;
    return off ^ ((off >> 3) & 0x70);
}
__device__ __forceinline__ uint32_t blk64_off(int row, int col) {
    uint32_t off = (uint32_t)(row >> 3) * 1024u
                 + (uint32_t)(row & 7) * 128u + (uint32_t)col * 2u;
    return off ^ ((off >> 3) & 0x70);
}

// ---------------- counting sort of edges by group ----------------
__global__ void hist_kernel(const int* __restrict__ gidx) {
    int e = blockIdx.x * 256 + threadIdx.x;
    if (e < EE) atomicAdd(&g_cnt[gidx[e]], 1);
}

__global__ void scan_kernel() {
    __shared__ int part[1024];
    int tid = threadIdx.x;
    int c0 = tid * 6;
    int local[6];
    int s = 0;
    #pragma unroll
    for (int i = 0; i < 6; i++) {
        int v = (c0 + i < GG) ? g_cnt[c0 + i] : 0;
        local[i] = s; s += v;
    }
    part[tid] = s;
    __syncthreads();
    for (int off = 1; off < 1024; off <<= 1) {
        int v = (tid >= off) ? part[tid - off] : 0;
        __syncthreads();
        part[tid] += v;
        __syncthreads();
    }
    int base = (tid > 0) ? part[tid - 1] : 0;
    #pragma unroll
    for (int i = 0; i < 6; i++)
        if (c0 + i < GG) g_cur[c0 + i] = base + local[i];
}

__global__ void scatter_kernel(const int* __restrict__ gidx) {
    int e = blockIdx.x * 256 + threadIdx.x;
    if (e < EE) {
        int pos = atomicAdd(&g_cur[gidx[e]], 1);
        g_perm[pos] = e;
    }
}

// ---------------- weight conversions ----------------
__global__ void wconv_kernel(
    const float* __restrict__ W0, const float* __restrict__ W1,
    const float* __restrict__ W2, const float* __restrict__ W3,
    const float* __restrict__ W4, const float* __restrict__ W5,
    const float* __restrict__ W6, const float* __restrict__ W7,
    const float* __restrict__ W8)
{
    const float* Ws[9] = {W0, W1, W2, W3, W4, W5, W6, W7, W8};
    int gidx = blockIdx.x * 256 + threadIdx.x;
    if (gidx >= 9 * 8192) return;
    int w = gidx >> 13, p = gidx & 8191;
    int n = p >> 6, k2 = (p & 63) * 2;
    const float* W = Ws[w];
    float x0 = W[k2 * 128 + n], x1 = W[(k2 + 1) * 128 + n];
    __nv_bfloat16 h0 = __float2bfloat16(x0), h1 = __float2bfloat16(x1);
    float r0 = x0 - __bfloat162float(h0), r1 = x1 - __bfloat162float(h1);
    __nv_bfloat16 l0 = __float2bfloat16(r0), l1 = __float2bfloat16(r1);
    uint32_t o = blk_off(n, k2) >> 2;
    g_whi[w * 8192 + o] = (uint32_t)__bfloat16_as_ushort(h0)
                        | ((uint32_t)__bfloat16_as_ushort(h1) << 16);
    g_wlo[w * 8192 + o] = (uint32_t)__bfloat16_as_ushort(l0)
                        | ((uint32_t)__bfloat16_as_ushort(l1) << 16);
}

__global__ void wconv2_kernel(const float* __restrict__ Wp2,
                              const float* __restrict__ Ws2)
{
    int gidx = blockIdx.x * 256 + threadIdx.x;
    if (gidx >= 2 * 4096) return;
    int w = gidx >> 12, p = gidx & 4095;
    int n = p >> 5, k2 = (p & 31) * 2;
    const float* W = w ? Ws2 : Wp2;
    float x0 = W[k2 * 128 + n], x1 = W[(k2 + 1) * 128 + n];
    __nv_bfloat16 h0 = __float2bfloat16(x0), h1 = __float2bfloat16(x1);
    float r0 = x0 - __bfloat162float(h0), r1 = x1 - __bfloat162float(h1);
    __nv_bfloat16 l0 = __float2bfloat16(r0), l1 = __float2bfloat16(r1);
    uint32_t o = blk64_off(n, k2) >> 2;
    g_w2hi[w * 4096 + o] = (uint32_t)__bfloat16_as_ushort(h0)
                         | ((uint32_t)__bfloat16_as_ushort(h1) << 16);
    g_w2lo[w * 4096 + o] = (uint32_t)__bfloat16_as_ushort(l0)
                         | ((uint32_t)__bfloat16_as_ushort(l1) << 16);
}

// ---------------- arch helpers ----------------
#if defined(__CUDA_ARCH_FEAT_SM103_ALL) || !defined(__CUDA_ARCH__)
#define HAVE_TCGEN05 1
#else
#define HAVE_TCGEN05 0
#endif

__device__ __forceinline__ uint32_t smem_u32(const void* p) {
    uint32_t a;
    asm("{ .reg .u64 t; cvta.to.shared.u64 t, %1; cvt.u32.u64 %0, t; }"
        : "=r"(a) : "l"(p));
    return a;
}

#if HAVE_TCGEN05
__device__ __forceinline__ uint32_t elect1() {
    uint32_t p;
    asm volatile("{\n\t.reg .pred p;\n\telect.sync _|p, 0xFFFFFFFF;\n\t"
                 "selp.b32 %0, 1, 0, p;\n\t}" : "=r"(p));
    return p;
}
__device__ __forceinline__ void mma_f16_ss(uint32_t d, uint64_t a, uint64_t b,
                                           uint32_t idesc, uint32_t en) {
    asm volatile("{\n\t.reg .pred p;\n\tsetp.ne.u32 p, %5, 0;\n\t"
                 "tcgen05.mma.cta_group::1.kind::f16 [%0], %1, %2, %3, {%4,%4,%4,%4}, p;\n\t}"
                 :: "r"(d), "l"(a), "l"(b), "r"(idesc), "r"(0u), "r"(en) : "memory");
}
__device__ __forceinline__ void mbar_wait(uint32_t mbar, uint32_t parity) {
    uint32_t done;
    asm volatile("{\n\t.reg .pred p;\n\t"
                 "mbarrier.try_wait.parity.acquire.cta.shared::cta.b64 p, [%1], %2;\n\t"
                 "selp.b32 %0, 1, 0, p;\n\t}"
                 : "=r"(done) : "r"(mbar), "r"(parity) : "memory");
    if (!done) {
        asm volatile("{\n\t.reg .pred P1;\n\t"
                     "WAIT_LOOP_%=:\n\t"
                     "mbarrier.try_wait.parity.acquire.cta.shared::cta.b64 P1, [%0], %1, 0x989680;\n\t"
                     "@P1 bra.uni WAIT_DONE_%=;\n\t"
                     "bra.uni WAIT_LOOP_%=;\n\t"
                     "WAIT_DONE_%=:\n\t}"
                     :: "r"(mbar), "r"(parity) : "memory");
    }
}
#define LDTM_X32(r, addr) \
    asm volatile( \
        "tcgen05.ld.sync.aligned.32x32b.x32.b32 " \
        "{%0, %1, %2, %3, %4, %5, %6, %7, " \
        " %8, %9, %10, %11, %12, %13, %14, %15, " \
        " %16, %17, %18, %19, %20, %21, %22, %23, " \
        " %24, %25, %26, %27, %28, %29, %30, %31}, [%32];" \
        : "=r"((r)[0]),  "=r"((r)[1]),  "=r"((r)[2]),  "=r"((r)[3]), \
          "=r"((r)[4]),  "=r"((r)[5]),  "=r"((r)[6]),  "=r"((r)[7]), \
          "=r"((r)[8]),  "=r"((r)[9]),  "=r"((r)[10]), "=r"((r)[11]), \
          "=r"((r)[12]), "=r"((r)[13]), "=r"((r)[14]), "=r"((r)[15]), \
          "=r"((r)[16]), "=r"((r)[17]), "=r"((r)[18]), "=r"((r)[19]), \
          "=r"((r)[20]), "=r"((r)[21]), "=r"((r)[22]), "=r"((r)[23]), \
          "=r"((r)[24]), "=r"((r)[25]), "=r"((r)[26]), "=r"((r)[27]), \
          "=r"((r)[28]), "=r"((r)[29]), "=r"((r)[30]), "=r"((r)[31]) \
        : "r"(addr))
#endif  // HAVE_TCGEN05

// ---------------- pipelined tcgen05 GEMM (unchanged, proven) ----------------
#define SM_TMEM 0
#define SM_MB0  8
#define SM_MB1  16
#define SM_MB2  24
#define SM_AHI  1024
#define SM_ALO  33792
#define SM_B0HI 66560
#define SM_B0LO 99328
#define SM_B1HI 132096
#define SM_B1LO 164864
#define TC_SMEM 197632
#define TMEM_COLS 512

#if HAVE_TCGEN05
__device__ __forceinline__ void tc_copyB(char* smem, uint32_t dsthi, uint32_t dstlo,
                                         int w, int tid)
{
    const uint4* shi = (const uint4*)(g_whi + w * 8192);
    const uint4* slo = (const uint4*)(g_wlo + w * 8192);
    uint4* dhi = (uint4*)(smem + dsthi);
    uint4* dlo = (uint4*)(smem + dstlo);
    for (int i = tid; i < 2048; i += 256) { dhi[i] = shi[i]; dlo[i] = slo[i]; }
}

__device__ __forceinline__ void tc_issue_mma(uint32_t tmem_d, uint64_t ahi, uint64_t alo,
                                             uint64_t bhi, uint64_t blo, uint32_t mbar)
{
    const uint32_t IDESC = (1u << 4) | (1u << 7) | (1u << 10) | (16u << 17) | (8u << 24);
    uint32_t en = 0;
    #pragma unroll
    for (int kc = 0; kc < 8; kc++) {
        uint64_t ko = (uint64_t)((kc & 3) * 2 + (kc >> 2) * 1024);
        mma_f16_ss(tmem_d, ahi + ko, bhi + ko, IDESC, en); en = 1;
    }
    #pragma unroll
    for (int kc = 0; kc < 8; kc++) {
        uint64_t ko = (uint64_t)((kc & 3) * 2 + (kc >> 2) * 1024);
        mma_f16_ss(tmem_d, ahi + ko, blo + ko, IDESC, 1);
    }
    #pragma unroll
    for (int kc = 0; kc < 8; kc++) {
        uint64_t ko = (uint64_t)((kc & 3) * 2 + (kc >> 2) * 1024);
        mma_f16_ss(tmem_d, alo + ko, bhi + ko, IDESC, 1);
    }
    asm volatile("tcgen05.commit.cta_group::1.mbarrier::arrive::one.shared::cluster.b64 [%0];"
                 :: "r"(mbar) : "memory");
}

__device__ __forceinline__ void tc_epilogue(uint32_t tmem_d, int M, int row0,
                                            int wid, int lane, int mode,
                                            const float* bias, float* C)
{
    if (wid >= 4) return;
    int gr = row0 + wid * 32 + lane;
    #pragma unroll 1
    for (int cb = 0; cb < 4; cb++) {
        uint32_t d[32];
        LDTM_X32(d, tmem_d + cb * 32);
        asm volatile("tcgen05.wait::ld.sync.aligned;" ::: "memory");
        if (gr < M) {
            float* dst = C + (size_t)gr * 128 + cb * 32;
            if (mode == 1) {
                const float4* mvp = (const float4*)(g_mv + (size_t)gr * 128 + cb * 32);
                const float4* t0p = (const float4*)(g_t0 + (size_t)(gr / 3) * 128 + cb * 32);
                #pragma unroll
                for (int q = 0; q < 8; q++) {
                    float4 mv = mvp[q], t0 = t0p[q];
                    float4 o;
                    o.x = mv.x + t0.x * __uint_as_float(d[q * 4 + 0]);
                    o.y = mv.y + t0.y * __uint_as_float(d[q * 4 + 1]);
                    o.z = mv.z + t0.z * __uint_as_float(d[q * 4 + 2]);
                    o.w = mv.w + t0.w * __uint_as_float(d[q * 4 + 3]);
                    ((float4*)dst)[q] = o;
                }
            } else {
                #pragma unroll
                for (int q = 0; q < 8; q++) {
                    float4 o;
                    o.x = __uint_as_float(d[q * 4 + 0]);
                    o.y = __uint_as_float(d[q * 4 + 1]);
                    o.z = __uint_as_float(d[q * 4 + 2]);
                    o.w = __uint_as_float(d[q * 4 + 3]);
                    if (bias) {
                        const float* bb = bias + cb * 32 + q * 4;
                        o.x += bb[0]; o.y += bb[1]; o.z += bb[2]; o.w += bb[3];
                    }
                    ((float4*)dst)[q] = o;
                }
            }
        }
    }
}
#endif  // HAVE_TCGEN05

__global__ __launch_bounds__(256, 1) __cluster_dims__(1, 1, 1)
void tc_gemm(const float* __restrict__ A, int M,
             int w0, int m0, const float* __restrict__ W0f, const float* __restrict__ b0, float* __restrict__ C0,
             int w1, int m1, const float* __restrict__ W1f, const float* __restrict__ b1, float* __restrict__ C1,
             int w2, int m2, const float* __restrict__ W2f, const float* __restrict__ b2, float* __restrict__ C2)
{
#if HAVE_TCGEN05
    extern __shared__ char smem[];
    uint32_t sb = smem_u32(smem);
    int tid = threadIdx.x, wid = tid >> 5, lane = tid & 31;
    int row0 = blockIdx.x * 128;

    if (wid == 0)
        asm volatile("tcgen05.alloc.cta_group::1.sync.aligned.shared::cta.b32 [%0], %1;"
                     :: "r"(sb + SM_TMEM), "r"((uint32_t)TMEM_COLS) : "memory");
    if (tid == 0) {
        asm volatile("mbarrier.init.shared.b64 [%0], 1;" :: "r"(sb + SM_MB0) : "memory");
        asm volatile("mbarrier.init.shared.b64 [%0], 1;" :: "r"(sb + SM_MB1) : "memory");
        asm volatile("mbarrier.init.shared.b64 [%0], 1;" :: "r"(sb + SM_MB2) : "memory");
    }
    __syncthreads();
    uint32_t tmem;
    asm volatile("ld.shared.b32 %0, [%1];" : "=r"(tmem) : "r"(sb + SM_TMEM));

    for (int p = tid; p < 8192; p += 256) {
        int r = p >> 6, k2 = (p & 63) * 2;
        float2 x = make_float2(0.f, 0.f);
        if (row0 + r < M) x = *(const float2*)(A + (size_t)(row0 + r) * 128 + k2);
        __nv_bfloat16 h0 = __float2bfloat16(x.x), h1 = __float2bfloat16(x.y);
        float r0f = x.x - __bfloat162float(h0), r1f = x.y - __bfloat162float(h1);
        __nv_bfloat16 l0 = __float2bfloat16(r0f), l1 = __float2bfloat16(r1f);
        uint32_t hiw = (uint32_t)__bfloat16_as_ushort(h0)
                     | ((uint32_t)__bfloat16_as_ushort(h1) << 16);
        uint32_t low = (uint32_t)__bfloat16_as_ushort(l0)
                     | ((uint32_t)__bfloat16_as_ushort(l1) << 16);
        uint32_t off = blk_off(r, k2);
        *(uint32_t*)(smem + SM_AHI + off) = hiw;
        *(uint32_t*)(smem + SM_ALO + off) = low;
    }

    const uint64_t DESCB = (2ull << 61) | (1ull << 46) | (64ull << 32) | (1ull << 16);
    uint64_t ahi  = DESCB | ((uint64_t)((sb + SM_AHI)  >> 4) & 0x3FFF);
    uint64_t alo  = DESCB | ((uint64_t)((sb + SM_ALO)  >> 4) & 0x3FFF);
    uint64_t b0hi = DESCB | ((uint64_t)((sb + SM_B0HI) >> 4) & 0x3FFF);
    uint64_t b0lo = DESCB | ((uint64_t)((sb + SM_B0LO) >> 4) & 0x3FFF);
    uint64_t b1hi = DESCB | ((uint64_t)((sb + SM_B1HI) >> 4) & 0x3FFF);
    uint64_t b1lo = DESCB | ((uint64_t)((sb + SM_B1LO) >> 4) & 0x3FFF);

    tc_copyB(smem, SM_B0HI, SM_B0LO, w0, tid);
    asm volatile("fence.proxy.async.shared::cta;" ::: "memory");
    __syncthreads();
    if (wid == 0 && elect1())
        tc_issue_mma(tmem, ahi, alo, b0hi, b0lo, sb + SM_MB0);

    if (w1 >= 0) {
        tc_copyB(smem, SM_B1HI, SM_B1LO, w1, tid);
        asm volatile("fence.proxy.async.shared::cta;" ::: "memory");
        __syncthreads();
        if (wid == 0 && elect1())
            tc_issue_mma(tmem + 128, ahi, alo, b1hi, b1lo, sb + SM_MB1);
    }

    mbar_wait(sb + SM_MB0, 0);
    asm volatile("tcgen05.fence::after_thread_sync;" ::: "memory");
    if (w2 >= 0) {
        tc_copyB(smem, SM_B0HI, SM_B0LO, w2, tid);
        asm volatile("fence.proxy.async.shared::cta;" ::: "memory");
        __syncthreads();
        if (wid == 0 && elect1())
            tc_issue_mma(tmem + 256, ahi, alo, b0hi, b0lo, sb + SM_MB2);
    }

    tc_epilogue(tmem, M, row0, wid, lane, m0, b0, C0);
    if (w1 >= 0) {
        mbar_wait(sb + SM_MB1, 0);
        asm volatile("tcgen05.fence::after_thread_sync;" ::: "memory");
        tc_epilogue(tmem + 128, M, row0, wid, lane, m1, b1, C1);
    }
    if (w2 >= 0) {
        mbar_wait(sb + SM_MB2, 0);
        asm volatile("tcgen05.fence::after_thread_sync;" ::: "memory");
        tc_epilogue(tmem + 256, M, row0, wid, lane, m2, b2, C2);
    }
    asm volatile("tcgen05.fence::before_thread_sync;" ::: "memory");
    __syncthreads();

    if (tid == 0) {
        asm volatile("mbarrier.inval.shared.b64 [%0];" :: "r"(sb + SM_MB0) : "memory");
        asm volatile("mbarrier.inval.shared.b64 [%0];" :: "r"(sb + SM_MB1) : "memory");
        asm volatile("mbarrier.inval.shared.b64 [%0];" :: "r"(sb + SM_MB2) : "memory");
    }
    __syncthreads();
    if (wid == 0)
        asm volatile("tcgen05.dealloc.cta_group::1.sync.aligned.b32 %0, %1;"
                     :: "r"(tmem), "r"((uint32_t)TMEM_COLS));

#else  // SIMT fp32 fallback
    extern __shared__ float smf[];
    float* sA = smf;
    float* sW = smf + 16384;
    int tid = threadIdx.x;
    int row0 = blockIdx.x * 128;

    for (int i = tid; i < 4096; i += 256) {
        int r  = i >> 5;
        int gr = row0 + r;
        float4 v = make_float4(0.f, 0.f, 0.f, 0.f);
        if (gr < M) v = ((const float4*)A)[(size_t)gr * 32 + (i & 31)];
        ((float4*)sA)[i] = v;
    }

    const float* Wf[3] = {W0f, W1f, W2f};
    const float* bpf[3] = {b0, b1, b2};
    float* cpf[3] = {C0, C1, C2};
    int widxf[3] = {w0, w1, w2};
    int modef[3] = {m0, m1, m2};

    #pragma unroll 1
    for (int j = 0; j < 3; j++) {
        if (widxf[j] < 0) break;
        __syncthreads();
        for (int i = tid; i < 4096; i += 256)
            ((float4*)sW)[i] = ((const float4*)Wf[j])[i];
        __syncthreads();

        int rb = tid >> 4, cb = tid & 15;
        float acc[8][8];
        #pragma unroll
        for (int i = 0; i < 8; i++)
            #pragma unroll
            for (int q = 0; q < 8; q++) acc[i][q] = 0.f;

        #pragma unroll 4
        for (int k = 0; k < 128; k++) {
            float4 wv0 = *(const float4*)&sW[k * 128 + cb * 8];
            float4 wv1 = *(const float4*)&sW[k * 128 + cb * 8 + 4];
            float w[8] = {wv0.x, wv0.y, wv0.z, wv0.w, wv1.x, wv1.y, wv1.z, wv1.w};
            float a[8];
            #pragma unroll
            for (int i = 0; i < 8; i++) a[i] = sA[(rb * 8 + i) * 128 + k];
            #pragma unroll
            for (int i = 0; i < 8; i++)
                #pragma unroll
                for (int q = 0; q < 8; q++) acc[i][q] += a[i] * w[q];
        }

        #pragma unroll
        for (int i = 0; i < 8; i++) {
            int gr = row0 + rb * 8 + i;
            if (gr < M) {
                float* dst = cpf[j] + (size_t)gr * 128 + cb * 8;
                for (int q = 0; q < 8; q++) {
                    float o = acc[i][q];
                    if (modef[j] == 1)
                        o = g_mv[(size_t)gr * 128 + cb * 8 + q]
                          + g_t0[(size_t)(gr / 3) * 128 + cb * 8 + q] * o;
                    else if (bpf[j]) o += bpf[j][cb * 8 + q];
                    dst[q] = o;
                }
            }
        }
    }
#endif
}

// ---------------- P precompute ----------------
__global__ void pprep_kernel(const float* __restrict__ Wp1,
                             const float* __restrict__ Ws1)
{
    int idx = blockIdx.x * blockDim.x + threadIdx.x;
    if (idx >= GG * 512) return;
    int g  = idx >> 9;
    int hc = idx & 511;
    int h  = hc >> 6, c = hc & 63;
    const float* vp = g_val + (size_t)g * 128 + h * 16;
    float sp = 0.f, ss = 0.f;
    #pragma unroll
    for (int i = 0; i < 16; i++) {
        float v = vp[i];
        int wrow = (h * 16 + i) * 64 + c;
        sp += v * Wp1[wrow];
        ss += v * Ws1[wrow];
    }
    g_Pp[idx] = sp;
    g_Ps[idx] = ss;
}

// ---------------- fused edge kernel: pipelined tiles, 16-warp epilogue ----------------
#define XO_W2PH 0
#define XO_W2PL 16384
#define XO_W2SH 32768
#define XO_W2SL 49152
#define XO_AHPH 65536
#define XO_AHPL 81920
#define XO_AHSH 98304
#define XO_AHSL 114688
#define XO_ATT  131072    // 4KB attn [128][8]
#define XO_U    135168    // 2 x [128][3] = 3072B
#define XO_N    138240    // 2 x 128 int
#define XO_G    139264    // 2 x 128 int
#define XO_E    140288    // 128 int
#define XO_BP1  140800
#define XO_BS1  141056
#define XO_BP2  141312
#define XO_BS2  141824
#define XO_TM   142336
#define XO_MBAR 142344    // 2 mbarriers
#define EDGE_SMEM_BYTES 142400
#define ETILE 128
#define NTILES (EE / ETILE)   // 3125

__global__ __launch_bounds__(512, 1) __cluster_dims__(1, 1, 1)
void edge_kernel(
    const int*   __restrict__ node_idx,
    const int*   __restrict__ group_idx,
    const float* __restrict__ edge_attr,
    const float* __restrict__ edge_vec,
    const float* __restrict__ bp1, const float* __restrict__ bs1,
    const float* __restrict__ Wp2, const float* __restrict__ bp2,
    const float* __restrict__ Ws2, const float* __restrict__ bs2,
    const float* __restrict__ gvec)
{
    extern __shared__ char smx[];
    uint32_t sb = smem_u32(smx);
    int tid = threadIdx.x, wid = tid >> 5, lane = tid & 31;

    float* s_attn = (float*)(smx + XO_ATT);
    int*   s_e    = (int*)(smx + XO_E);
    float* s_bp1  = (float*)(smx + XO_BP1);
    float* s_bs1  = (float*)(smx + XO_BS1);
    float* s_bp2  = (float*)(smx + XO_BP2);
    float* s_bs2  = (float*)(smx + XO_BS2);

    if (tid < 64)  { s_bp1[tid] = bp1[tid]; s_bs1[tid] = bs1[tid]; }
    if (tid < 128) { s_bp2[tid] = bp2[tid]; s_bs2[tid] = bs2[tid]; }

#if HAVE_TCGEN05
    for (int i = tid; i < 1024; i += 512) {
        ((uint4*)(smx + XO_W2PH))[i] = ((const uint4*)g_w2hi)[i];
        ((uint4*)(smx + XO_W2PL))[i] = ((const uint4*)g_w2lo)[i];
        ((uint4*)(smx + XO_W2SH))[i] = ((const uint4*)g_w2hi)[1024 + i];
        ((uint4*)(smx + XO_W2SL))[i] = ((const uint4*)g_w2lo)[1024 + i];
    }
    if (wid == 0)
        asm volatile("tcgen05.alloc.cta_group::1.sync.aligned.shared::cta.b32 [%0], %1;"
                     :: "r"(sb + XO_TM), "r"((uint32_t)TMEM_COLS) : "memory");
    if (tid == 0) {
        asm volatile("mbarrier.init.shared.b64 [%0], 1;" :: "r"(sb + XO_MBAR) : "memory");
        asm volatile("mbarrier.init.shared.b64 [%0], 1;" :: "r"(sb + XO_MBAR + 8) : "memory");
    }
    __syncthreads();
    uint32_t tmem;
    asm volatile("ld.shared.b32 %0, [%1];" : "=r"(tmem) : "r"(sb + XO_TM));

    const uint64_t DESCB = (2ull << 61) | (1ull << 46) | (64ull << 32) | (1ull << 16);
    uint64_t aph = DESCB | ((uint64_t)((sb + XO_AHPH) >> 4) & 0x3FFF);
    uint64_t apl = DESCB | ((uint64_t)((sb + XO_AHPL) >> 4) & 0x3FFF);
    uint64_t ash = DESCB | ((uint64_t)((sb + XO_AHSH) >> 4) & 0x3FFF);
    uint64_t asl = DESCB | ((uint64_t)((sb + XO_AHSL) >> 4) & 0x3FFF);
    uint64_t wph = DESCB | ((uint64_t)((sb + XO_W2PH) >> 4) & 0x3FFF);
    uint64_t wpl = DESCB | ((uint64_t)((sb + XO_W2PL) >> 4) & 0x3FFF);
    uint64_t wsh = DESCB | ((uint64_t)((sb + XO_W2SH) >> 4) & 0x3FFF);
    uint64_t wsl = DESCB | ((uint64_t)((sb + XO_W2SL) >> 4) & 0x3FFF);
    const uint32_t IDESC = (1u << 4) | (1u << 7) | (1u << 10) | (16u << 17) | (8u << 24);
    uint32_t phz[2] = {0, 0};
#else
    __syncthreads();
#endif

    int it = 0;
    for (int t = blockIdx.x; t < NTILES; t += gridDim.x, it++) {
        int buf = it & 1;
        int*   sn = (int*)(smx + XO_N) + buf * 128;
        int*   sg = (int*)(smx + XO_G) + buf * 128;
        float* su = (float*)(smx + XO_U) + buf * 384;

        // P0: edge metadata (group-sorted)
        if (tid < 128) {
            int e = g_perm[t * ETILE + tid];
            s_e[tid] = e;
            sn[tid] = node_idx[e];
            sg[tid] = group_idx[e];
            su[tid * 3 + 0] = -edge_vec[e * 3 + 0];
            su[tid * 3 + 1] = -edge_vec[e * 3 + 1];
            su[tid * 3 + 2] = -edge_vec[e * 3 + 2];
        }
        __syncthreads();

        // P1: attention (128 edges x 8 heads, 2 per thread)
        {
            float dots[2];
            #pragma unroll
            for (int r = 0; r < 2; r++) {
                int p = tid + r * 512;
                int le = p >> 3, h = p & 7;
                const float4* qp = (const float4*)(g_q + (size_t)sn[le] * 128 + h * 16);
                const float4* kp = (const float4*)(g_k + (size_t)sg[le] * 128 + h * 16);
                const float4* ep = (const float4*)(edge_attr + (size_t)s_e[le] * 128 + h * 16);
                float dot = 0.f;
                #pragma unroll
                for (int c = 0; c < 4; c++) {
                    float4 qv = qp[c], kv = kp[c], ev = ep[c];
                    dot += qv.x * kv.x * ev.x + qv.y * kv.y * ev.y
                         + qv.z * kv.z * ev.z + qv.w * kv.w * ev.w;
                }
                dots[r] = silu_f(dot * 0.25f);
            }
            s_attn[tid] = dots[0];
            s_attn[tid + 512] = dots[1];
        }
        __syncthreads();

        // P2: m_s scatter
        for (int i4 = tid; i4 < 4096; i4 += 512) {
            int le = i4 >> 5, j4 = i4 & 31;
            float4 v = ((const float4*)(g_val + (size_t)sg[le] * 128))[j4];
            float  a = s_attn[le * 8 + (j4 >> 2)];
            float4 m = make_float4(v.x * a, v.y * a, v.z * a, v.w * a);
            atomicAdd((float4*)(g_ms + (size_t)sn[le] * 128 + j4 * 4), m);
        }

        // P3a: layer-1 into registers
        float hp[16], hs[16];
        {
            int le = tid >> 2, cq = tid & 3;
            int g = sg[le];
            float at[8];
            #pragma unroll
            for (int h = 0; h < 8; h++) at[h] = s_attn[le * 8 + h];
            #pragma unroll
            for (int j = 0; j < 16; j++) { hp[j] = 0.f; hs[j] = 0.f; }
            const float4* Pp4 = (const float4*)(g_Pp + (size_t)g * 512);
            const float4* Ps4 = (const float4*)(g_Ps + (size_t)g * 512);
            #pragma unroll
            for (int h = 0; h < 8; h++) {
                int base = h * 16 + cq * 4;
                float ah = at[h];
                #pragma unroll
                for (int q = 0; q < 4; q++) {
                    float4 p = Pp4[base + q];
                    float4 s = Ps4[base + q];
                    hp[q*4+0] += ah * p.x; hp[q*4+1] += ah * p.y;
                    hp[q*4+2] += ah * p.z; hp[q*4+3] += ah * p.w;
                    hs[q*4+0] += ah * s.x; hs[q*4+1] += ah * s.y;
                    hs[q*4+2] += ah * s.z; hs[q*4+3] += ah * s.w;
                }
            }
        }

#if HAVE_TCGEN05
        // wait for MMA(it-1): frees hidden staging AND readies prev results
        if (it >= 1) {
            int pb = 1 - buf;
            mbar_wait(sb + XO_MBAR + pb * 8, phz[pb]);
            phz[pb] ^= 1;
            asm volatile("tcgen05.fence::after_thread_sync;" ::: "memory");
        }

        // P3b: write hidden bf16 hi/lo
        {
            int le = tid >> 2, cq = tid & 3, c0 = cq * 16;
            #pragma unroll
            for (int jp = 0; jp < 8; jp++) {
                float p0 = silu_f(hp[jp*2]   + s_bp1[c0 + jp*2]);
                float p1 = silu_f(hp[jp*2+1] + s_bp1[c0 + jp*2+1]);
                float q0 = silu_f(hs[jp*2]   + s_bs1[c0 + jp*2]);
                float q1 = silu_f(hs[jp*2+1] + s_bs1[c0 + jp*2+1]);
                __nv_bfloat16 ph0 = __float2bfloat16(p0), ph1 = __float2bfloat16(p1);
                __nv_bfloat16 qh0 = __float2bfloat16(q0), qh1 = __float2bfloat16(q1);
                float pr0 = p0 - __bfloat162float(ph0), pr1 = p1 - __bfloat162float(ph1);
                float qr0 = q0 - __bfloat162float(qh0), qr1 = q1 - __bfloat162float(qh1);
                __nv_bfloat16 pl0 = __float2bfloat16(pr0), pl1 = __float2bfloat16(pr1);
                __nv_bfloat16 ql0 = __float2bfloat16(qr0), ql1 = __float2bfloat16(qr1);
                uint32_t off = blk64_off(tid >> 2, c0 + jp * 2);
                *(uint32_t*)(smx + XO_AHPH + off) =
                    (uint32_t)__bfloat16_as_ushort(ph0) | ((uint32_t)__bfloat16_as_ushort(ph1) << 16);
                *(uint32_t*)(smx + XO_AHPL + off) =
                    (uint32_t)__bfloat16_as_ushort(pl0) | ((uint32_t)__bfloat16_as_ushort(pl1) << 16);
                *(uint32_t*)(smx + XO_AHSH + off) =
                    (uint32_t)__bfloat16_as_ushort(qh0) | ((uint32_t)__bfloat16_as_ushort(qh1) << 16);
                *(uint32_t*)(smx + XO_AHSL + off) =
                    (uint32_t)__bfloat16_as_ushort(ql0) | ((uint32_t)__bfloat16_as_ushort(ql1) << 16);
            }
        }
        asm volatile("fence.proxy.async.shared::cta;" ::: "memory");
        __syncthreads();

        // MMA(it) into TMEM half buf
        uint32_t tmb = tmem + 256 * buf;
        if (wid == 0 && elect1()) {
            uint32_t en = 0;
            #pragma unroll
            for (int kc = 0; kc < 4; kc++) {
                uint64_t ko = (uint64_t)(kc * 2);
                mma_f16_ss(tmb, aph + ko, wph + ko, IDESC, en); en = 1;
            }
            #pragma unroll
            for (int kc = 0; kc < 4; kc++) {
                uint64_t ko = (uint64_t)(kc * 2);
                mma_f16_ss(tmb, aph + ko, wpl + ko, IDESC, 1);
                mma_f16_ss(tmb, apl + ko, wph + ko, IDESC, 1);
            }
            en = 0;
            #pragma unroll
            for (int kc = 0; kc < 4; kc++) {
                uint64_t ko = (uint64_t)(kc * 2);
                mma_f16_ss(tmb + 128, ash + ko, wsh + ko, IDESC, en); en = 1;
            }
            #pragma unroll
            for (int kc = 0; kc < 4; kc++) {
                uint64_t ko = (uint64_t)(kc * 2);
                mma_f16_ss(tmb + 128, ash + ko, wsl + ko, IDESC, 1);
                mma_f16_ss(tmb + 128, asl + ko, wsh + ko, IDESC, 1);
            }
            asm volatile("tcgen05.commit.cta_group::1.mbarrier::arrive::one.shared::cluster.b64 [%0];"
                         :: "r"(sb + XO_MBAR + buf * 8) : "memory");
        }

        // epilogue for tile it-1 (overlaps MMA(it)): 16 warps
        if (it >= 1) {
            int pb = 1 - buf;
            int*   pn = (int*)(smx + XO_N) + pb * 128;
            int*   pg = (int*)(smx + XO_G) + pb * 128;
            float* pu = (float*)(smx + XO_U) + pb * 384;
            uint32_t tmp = tmem + 256 * pb;
            int spp = wid & 3, cbc = wid >> 2;
            int le = spp * 32 + lane;
            int n = pn[le], g = pg[le];
            float uu[3] = {pu[le * 3], pu[le * 3 + 1], pu[le * 3 + 2]};
            uint32_t dsp[32], dsv[32];
            LDTM_X32(dsp, tmp + cbc * 32);
            LDTM_X32(dsv, tmp + 128 + cbc * 32);
            asm volatile("tcgen05.wait::ld.sync.aligned;" ::: "memory");
            float spv[32], svv[32];
            #pragma unroll
            for (int j = 0; j < 32; j++) {
                spv[j] = __uint_as_float(dsp[j]) + s_bp2[cbc * 32 + j];
                svv[j] = __uint_as_float(dsv[j]) + s_bs2[cbc * 32 + j];
            }
            #pragma unroll
            for (int d = 0; d < 3; d++) {
                const float4* gv4 = (const float4*)(gvec + (size_t)g * 384 + d * 128 + cbc * 32);
                float* dst = g_mv + (size_t)n * 384 + d * 128 + cbc * 32;
                float ud = uu[d];
                #pragma unroll
                for (int q = 0; q < 8; q++) {
                    float4 gv = gv4[q];
                    float4 o;
                    o.x = spv[q*4+0] * ud + svv[q*4+0] * gv.x;
                    o.y = spv[q*4+1] * ud + svv[q*4+1] * gv.y;
                    o.z = spv[q*4+2] * ud + svv[q*4+2] * gv.z;
                    o.w = spv[q*4+3] * ud + svv[q*4+3] * gv.w;
                    atomicAdd((float4*)(dst + q * 4), o);
                }
            }
            asm volatile("tcgen05.fence::before_thread_sync;" ::: "memory");
        }
        __syncthreads();   // protect prev-buffer metadata before next P0
#else
        // -------- fallback: SIMT layer-2 (sequential) --------
        {
            int le = tid >> 2, cq = tid & 3, c0 = cq * 16;
            float* fhp = (float*)(smx + XO_AHPH);
            float* fhs = (float*)(smx + XO_AHSH);
            #pragma unroll
            for (int j = 0; j < 16; j++) {
                fhp[le * 64 + c0 + j] = silu_f(hp[j] + s_bp1[c0 + j]);
                fhs[le * 64 + c0 + j] = silu_f(hs[j] + s_bs1[c0 + j]);
            }
        }
        __syncthreads();
        {
            const float* fhp = (const float*)(smx + XO_AHPH);
            const float* fhs = (const float*)(smx + XO_AHSH);
            int rg = tid >> 4, cg = tid & 15;
            float sp[4][8], sv[4][8];
            #pragma unroll
            for (int i = 0; i < 4; i++)
                #pragma unroll
                for (int j = 0; j < 8; j++) { sp[i][j] = 0.f; sv[i][j] = 0.f; }
            for (int k = 0; k < 64; k++) {
                float wp[8], ws[8];
                #pragma unroll
                for (int j = 0; j < 8; j++) {
                    wp[j] = Wp2[k * 128 + cg * 8 + j];
                    ws[j] = Ws2[k * 128 + cg * 8 + j];
                }
                #pragma unroll
                for (int i = 0; i < 4; i++) {
                    float hpv = fhp[(rg * 4 + i) * 64 + k];
                    float hsv = fhs[(rg * 4 + i) * 64 + k];
                    #pragma unroll
                    for (int j = 0; j < 8; j++) {
                        sp[i][j] += hpv * wp[j];
                        sv[i][j] += hsv * ws[j];
                    }
                }
            }
            #pragma unroll
            for (int i = 0; i < 4; i++) {
                int le = rg * 4 + i;
                int n = sn[le], g = sg[le];
                #pragma unroll
                for (int d = 0; d < 3; d++) {
                    float ud = su[le * 3 + d];
                    const float* gv = gvec + (size_t)g * 384 + d * 128 + cg * 8;
                    float* dst = g_mv + (size_t)n * 384 + d * 128 + cg * 8;
                    #pragma unroll
                    for (int j = 0; j < 8; j += 4) {
                        float4 o;
                        o.x = (sp[i][j+0] + s_bp2[cg*8+j+0]) * ud + (sv[i][j+0] + s_bs2[cg*8+j+0]) * gv[j+0];
                        o.y = (sp[i][j+1] + s_bp2[cg*8+j+1]) * ud + (sv[i][j+1] + s_bs2[cg*8+j+1]) * gv[j+1];
                        o.z = (sp[i][j+2] + s_bp2[cg*8+j+2]) * ud + (sv[i][j+2] + s_bs2[cg*8+j+2]) * gv[j+2];
                        o.w = (sp[i][j+3] + s_bp2[cg*8+j+3]) * ud + (sv[i][j+3] + s_bs2[cg*8+j+3]) * gv[j+3];
                        atomicAdd((float4*)(dst + j), o);
                    }
                }
            }
        }
        __syncthreads();
#endif
    }

#if HAVE_TCGEN05
    // drain: epilogue for the last tile
    if (it >= 1) {
        int pb = (it - 1) & 1;
        mbar_wait(sb + XO_MBAR + pb * 8, phz[pb]);
        phz[pb] ^= 1;
        asm volatile("tcgen05.fence::after_thread_sync;" ::: "memory");
        int*   pn = (int*)(smx + XO_N) + pb * 128;
        int*   pg = (int*)(smx + XO_G) + pb * 128;
        float* pu = (float*)(smx + XO_U) + pb * 384;
        uint32_t tmp = tmem + 256 * pb;
        int spp = wid & 3, cbc = wid >> 2;
        int le = spp * 32 + lane;
        int n = pn[le], g = pg[le];
        float uu[3] = {pu[le * 3], pu[le * 3 + 1], pu[le * 3 + 2]};
        uint32_t dsp[32], dsv[32];
        LDTM_X32(dsp, tmp + cbc * 32);
        LDTM_X32(dsv, tmp + 128 + cbc * 32);
        asm volatile("tcgen05.wait::ld.sync.aligned;" ::: "memory");
        float spv[32], svv[32];
        #pragma unroll
        for (int j = 0; j < 32; j++) {
            spv[j] = __uint_as_float(dsp[j]) + s_bp2[cbc * 32 + j];
            svv[j] = __uint_as_float(dsv[j]) + s_bs2[cbc * 32 + j];
        }
        #pragma unroll
        for (int d = 0; d < 3; d++) {
            const float4* gv4 = (const float4*)(gvec + (size_t)g * 384 + d * 128 + cbc * 32);
            float* dst = g_mv + (size_t)n * 384 + d * 128 + cbc * 32;
            float ud = uu[d];
            #pragma unroll
            for (int q = 0; q < 8; q++) {
                float4 gv = gv4[q];
                float4 o;
                o.x = spv[q*4+0] * ud + svv[q*4+0] * gv.x;
                o.y = spv[q*4+1] * ud + svv[q*4+1] * gv.y;
                o.z = spv[q*4+2] * ud + svv[q*4+2] * gv.z;
                o.w = spv[q*4+3] * ud + svv[q*4+3] * gv.w;
                atomicAdd((float4*)(dst + q * 4), o);
            }
        }
        asm volatile("tcgen05.fence::before_thread_sync;" ::: "memory");
    }
    __syncthreads();
    if (tid == 0) {
        asm volatile("mbarrier.inval.shared.b64 [%0];" :: "r"(sb + XO_MBAR) : "memory");
        asm volatile("mbarrier.inval.shared.b64 [%0];" :: "r"(sb + XO_MBAR + 8) : "memory");
    }
    __syncthreads();
    if (wid == 0)
        asm volatile("tcgen05.dealloc.cta_group::1.sync.aligned.b32 %0, %1;"
                     :: "r"(tmem), "r"((uint32_t)TMEM_COLS));
#endif
}

// ---------------- finalize: dx only ----------------
__global__ void finalize_kernel(float* __restrict__ out) {
    int idx = blockIdx.x * blockDim.x + threadIdx.x;
    if (idx >= NN * 32) return;
    int n = idx >> 5, j4 = idx & 31;
    size_t off = (size_t)n * 32 + j4;
    float4 t4 = ((const float4*)g_t4)[off];
    float4 t5 = ((const float4*)g_t5)[off];
    float4 s3 = make_float4(0.f, 0.f, 0.f, 0.f);
    #pragma unroll
    for (int d = 0; d < 3; d++) {
        size_t roff = ((size_t)n * 3 + d) * 32 + j4;
        float4 v1 = ((const float4*)g_v1)[roff];
        float4 v2 = ((const float4*)g_v2)[roff];
        s3.x += v1.x * v2.x; s3.y += v1.y * v2.y;
        s3.z += v1.z * v2.z; s3.w += v1.w * v2.w;
    }
    float4 dx = make_float4(s3.x * t4.x + t5.x, s3.y * t4.y + t5.y,
                            s3.z * t4.z + t5.z, s3.w * t4.w + t5.w);
    ((float4*)out)[off] = dx;
}

// ---------------- launch ----------------
extern "C" void kernel_launch(void* const* d_in, const int* in_sizes, int n_in,
                              void* d_out, int out_size)
{
    (void)in_sizes; (void)n_in; (void)out_size;
    const int*   node_idx   = (const int*)  d_in[0];
    const int*   group_idx  = (const int*)  d_in[1];
    const float* node_emb   = (const float*)d_in[2];
    const float* node_vec   = (const float*)d_in[3];
    const float* group_emb  = (const float*)d_in[4];
    const float* group_vec  = (const float*)d_in[5];
    const float* edge_attr  = (const float*)d_in[6];
    const float* edge_vec   = (const float*)d_in[8];
    const float* Wq  = (const float*)d_in[9];
    const float* bq  = (const float*)d_in[10];
    const float* Wk  = (const float*)d_in[11];
    const float* bk  = (const float*)d_in[12];
    const float* Wv  = (const float*)d_in[13];
    const float* bv  = (const float*)d_in[14];
    const float* Wp1 = (const float*)d_in[15];
    const float* bp1 = (const float*)d_in[16];
    const float* Wp2 = (const float*)d_in[17];
    const float* bp2 = (const float*)d_in[18];
    const float* Ws1 = (const float*)d_in[19];
    const float* bs1 = (const float*)d_in[20];
    const float* Ws2 = (const float*)d_in[21];
    const float* bs2 = (const float*)d_in[22];
    const float* L0  = (const float*)d_in[23];
    const float* L1  = (const float*)d_in[24];
    const float* L2  = (const float*)d_in[25];
    const float* L3  = (const float*)d_in[26];
    const float* L4  = (const float*)d_in[27];
    const float* L5  = (const float*)d_in[28];
    float* out = (float*)d_out;

    cudaFuncSetAttribute(tc_gemm, cudaFuncAttributeMaxDynamicSharedMemorySize, TC_SMEM);
    cudaFuncSetAttribute(edge_kernel, cudaFuncAttributeMaxDynamicSharedMemorySize,
                         EDGE_SMEM_BYTES);

    float *p_q, *p_k, *p_val, *p_ms, *p_mv, *p_t0, *p_t4, *p_t5, *p_v1, *p_v2;
    int *p_cnt;
    cudaGetSymbolAddress((void**)&p_q,  g_q);
    cudaGetSymbolAddress((void**)&p_k,  g_k);
    cudaGetSymbolAddress((void**)&p_val,g_val);
    cudaGetSymbolAddress((void**)&p_ms, g_ms);
    cudaGetSymbolAddress((void**)&p_mv, g_mv);
    cudaGetSymbolAddress((void**)&p_t0, g_t0);
    cudaGetSymbolAddress((void**)&p_t4, g_t4);
    cudaGetSymbolAddress((void**)&p_t5, g_t5);
    cudaGetSymbolAddress((void**)&p_v1, g_v1);
    cudaGetSymbolAddress((void**)&p_v2, g_v2);
    cudaGetSymbolAddress((void**)&p_cnt, g_cnt);

    float* out_dv = out + (size_t)NN * 128;

    // 1) zero accumulators + sort scratch
    cudaMemsetAsync(p_ms, 0, (size_t)NN * 128 * sizeof(float));
    cudaMemsetAsync(p_mv, 0, (size_t)NN * 384 * sizeof(float));
    cudaMemsetAsync(p_cnt, 0, (size_t)GG * sizeof(int));

    // 2) group-sort the edges
    hist_kernel<<<(EE + 255) / 256, 256>>>(group_idx);
    scan_kernel<<<1, 1024>>>();
    scatter_kernel<<<(EE + 255) / 256, 256>>>(group_idx);

    // 3) weight conversions
    wconv_kernel<<<(9 * 8192 + 255) / 256, 256>>>(Wq, Wk, Wv, L0, L1, L2, L3, L4, L5);
    wconv2_kernel<<<(2 * 4096 + 255) / 256, 256>>>(Wp2, Ws2);

    // 4) projections on tensor cores
    tc_gemm<<<(NN + 127) / 128, 256, TC_SMEM>>>(node_emb, NN,
        0, 0, Wq, bq, p_q,
        -1, 0, nullptr, nullptr, nullptr,
        -1, 0, nullptr, nullptr, nullptr);
    tc_gemm<<<(GG + 127) / 128, 256, TC_SMEM>>>(group_emb, GG,
        1, 0, Wk, bk, p_k,
        2, 0, Wv, bv, p_val,
        -1, 0, nullptr, nullptr, nullptr);

    // 5) per-group layer-1 factorization tables
    pprep_kernel<<<(GG * 512 + 255) / 256, 256>>>(Wp1, Ws1);

    // 6) fused edge pipeline (pipelined tiles, 16-warp epilogue)
    edge_kernel<<<148, 512, EDGE_SMEM_BYTES>>>(node_idx, group_idx, edge_attr, edge_vec,
                                               bp1, bs1, Wp2, bp2, Ws2, bs2, group_vec);

    // 7) node-side GEMMs
    tc_gemm<<<(NN + 127) / 128, 256, TC_SMEM>>>(p_ms, NN,
        3, 0, L0, nullptr, p_t0,
        7, 0, L4, nullptr, p_t4,
        8, 0, L5, nullptr, p_t5);
    tc_gemm<<<(3 * NN + 127) / 128, 256, TC_SMEM>>>(node_vec, 3 * NN,
        4, 1, L1, nullptr, out_dv,
        5, 0, L2, nullptr, p_v1,
        6, 0, L3, nullptr, p_v2);

    // 8) finalize dx
    finalize_kernel<<<(NN * 32 + 255) / 256, 256>>>(out);
}